// round 1
// baseline (speedup 1.0000x reference)
#include <cuda_runtime.h>
#include <math.h>

// Problem constants (fixed shapes)
#define BB 2
#define LL 4096
#define DM 512
#define NH 8
#define HD 64
#define SK 45                 // sample_k = n_top = min(5*ceil(ln(4096)), 4096)
#define BH (BB*NH)
#define NSEG 32
#define SEGL (LL/NSEG)        // 128
#define JSEGS 16              // j-splits for upd partial sums

// Scratch (device globals — no allocation allowed in kernel_launch)
__device__ float g_Q[BB*NH*LL*HD];
__device__ float g_K[BB*NH*LL*HD];
__device__ float g_V[BB*NH*LL*HD];
__device__ float g_m[BH*LL];
__device__ int   g_top[BH*SK];
__device__ float g_seg[BH*NSEG*HD];
__device__ float g_sc[BH*SK*LL];
__device__ float g_part[BH*JSEGS*SK*HD];

// ---------------------------------------------------------------------------
// K1: fused projection GEMM. z selects q/k/v. C = A[M,512] @ W[512,512] + bias
// Output written head-transposed into g_{Q,K,V}[b][h][l][d].
// 128x128 tile, BK=16, 256 threads, 8x8 microtile.
// ---------------------------------------------------------------------------
__global__ __launch_bounds__(256) void k_proj(
    const float* __restrict__ Xq, const float* __restrict__ Xk, const float* __restrict__ Xv,
    const float* __restrict__ Wq, const float* __restrict__ bq,
    const float* __restrict__ Wk, const float* __restrict__ bk,
    const float* __restrict__ Wv, const float* __restrict__ bv)
{
    const float* A; const float* W; const float* bias; float* dst;
    if (blockIdx.z == 0)      { A = Xq; W = Wq; bias = bq; dst = g_Q; }
    else if (blockIdx.z == 1) { A = Xk; W = Wk; bias = bk; dst = g_K; }
    else                      { A = Xv; W = Wv; bias = bv; dst = g_V; }

    __shared__ float As[16][128];
    __shared__ float Bs[16][128];

    int tid = threadIdx.x;
    int tx = tid & 15, ty = tid >> 4;
    int m0 = blockIdx.y * 128;
    int n0 = blockIdx.x * 128;

    float c[8][8];
    #pragma unroll
    for (int i = 0; i < 8; i++)
        #pragma unroll
        for (int j = 0; j < 8; j++) c[i][j] = 0.f;

    for (int k0 = 0; k0 < DM; k0 += 16) {
        // A tile 128x16 -> As transposed [k][m]
        #pragma unroll
        for (int t = 0; t < 2; t++) {
            int f = tid + t * 256;        // 512 float4 total
            int row = f >> 2;             // 0..127
            int c4  = (f & 3) * 4;        // 0,4,8,12
            float4 v = *(const float4*)&A[(size_t)(m0 + row) * DM + k0 + c4];
            As[c4 + 0][row] = v.x;
            As[c4 + 1][row] = v.y;
            As[c4 + 2][row] = v.z;
            As[c4 + 3][row] = v.w;
        }
        // B tile 16x128
        #pragma unroll
        for (int t = 0; t < 2; t++) {
            int f = tid + t * 256;
            int row = f >> 5;             // 0..15
            int c4  = (f & 31) * 4;
            *(float4*)&Bs[row][c4] = *(const float4*)&W[(size_t)(k0 + row) * DM + n0 + c4];
        }
        __syncthreads();
        #pragma unroll
        for (int k = 0; k < 16; k++) {
            float a[8], b[8];
            *(float4*)&a[0] = *(float4*)&As[k][ty * 8];
            *(float4*)&a[4] = *(float4*)&As[k][ty * 8 + 4];
            *(float4*)&b[0] = *(float4*)&Bs[k][tx * 8];
            *(float4*)&b[4] = *(float4*)&Bs[k][tx * 8 + 4];
            #pragma unroll
            for (int i = 0; i < 8; i++)
                #pragma unroll
                for (int j = 0; j < 8; j++)
                    c[i][j] += a[i] * b[j];
        }
        __syncthreads();
    }
    // store to [b,h,l,d]
    #pragma unroll
    for (int i = 0; i < 8; i++) {
        int mi = m0 + ty * 8 + i;
        int b_ = mi >> 12, l = mi & (LL - 1);
        #pragma unroll
        for (int j = 0; j < 8; j++) {
            int ni = n0 + tx * 8 + j;
            int h = ni >> 6, dd = ni & 63;
            dst[(((size_t)(b_ * NH + h) * LL) + l) * HD + dd] = c[i][j] + bias[ni];
        }
    }
}

// ---------------------------------------------------------------------------
// K2: sparse measurement m[bh][l] = max_s(q_l . k_{idx[l,s]}) - sum_s(...)/L
// One warp per l. q held per-lane (2 elems), warp xor-reduce per sample.
// ---------------------------------------------------------------------------
__global__ __launch_bounds__(256) void k_mscore(const int* __restrict__ idx) {
    int bh = blockIdx.y;
    int w = threadIdx.x >> 5, lane = threadIdx.x & 31;
    int l = blockIdx.x * 8 + w;
    const float* Qb = g_Q + (size_t)bh * LL * HD;
    const float* Kb = g_K + (size_t)bh * LL * HD;
    float q0 = Qb[l * HD + lane];
    float q1 = Qb[l * HD + lane + 32];
    float mx = -INFINITY, sm = 0.f;
    for (int s = 0; s < SK; s++) {
        int j = idx[l * SK + s];
        float p = q0 * Kb[j * HD + lane] + q1 * Kb[j * HD + lane + 32];
        #pragma unroll
        for (int o = 16; o; o >>= 1) p += __shfl_xor_sync(0xffffffffu, p, o);
        mx = fmaxf(mx, p);
        sm += p;
    }
    if (lane == 0) g_m[bh * LL + l] = mx - sm * (1.f / LL);
}

// ---------------------------------------------------------------------------
// K3: top-45 of 4096 per (b,h). Iterative argmax. Tie-break: smaller index
// (matches jax.lax.top_k).
// ---------------------------------------------------------------------------
__global__ __launch_bounds__(256) void k_topk() {
    __shared__ float sv[LL];
    __shared__ float rv[256];
    __shared__ int   ri[256];
    int bh = blockIdx.x, tid = threadIdx.x;
    for (int i = tid; i < LL; i += 256) sv[i] = g_m[bh * LL + i];
    __syncthreads();
    for (int t = 0; t < SK; t++) {
        float bv_ = -INFINITY; int bi = LL;
        for (int i = tid; i < LL; i += 256) {
            float v = sv[i];
            if (v > bv_) { bv_ = v; bi = i; }   // strict > keeps smaller index on tie
        }
        rv[tid] = bv_; ri[tid] = bi;
        __syncthreads();
        for (int off = 128; off; off >>= 1) {
            if (tid < off) {
                float ov = rv[tid + off]; int oi = ri[tid + off];
                if (ov > rv[tid] || (ov == rv[tid] && oi < ri[tid])) { rv[tid] = ov; ri[tid] = oi; }
            }
            __syncthreads();
        }
        if (tid == 0) { g_top[bh * SK + t] = ri[0]; sv[ri[0]] = -INFINITY; }
        __syncthreads();
    }
}

// ---------------------------------------------------------------------------
// K4: segmented inclusive cumsum of V along seq (local part), writes directly
// into out[b][l][h*64+d] and segment totals to g_seg.
// ---------------------------------------------------------------------------
__global__ __launch_bounds__(256) void k_cumsum_local(float* __restrict__ out) {
    __shared__ float tile[SEGL * HD];
    int seg = blockIdx.x, bh = blockIdx.y, tid = threadIdx.x;
    const float* Vb = g_V + (size_t)bh * LL * HD + (size_t)seg * SEGL * HD;
    for (int i = tid; i < SEGL * HD; i += 256) tile[i] = Vb[i];
    __syncthreads();
    if (tid < HD) {
        float acc = tile[tid];
        for (int l = 1; l < SEGL; l++) { acc += tile[l * HD + tid]; tile[l * HD + tid] = acc; }
        g_seg[((size_t)bh * NSEG + seg) * HD + tid] = acc;
    }
    __syncthreads();
    int b_ = bh >> 3, h = bh & 7;
    for (int i = tid; i < SEGL * HD; i += 256) {
        int l = seg * SEGL + (i >> 6), dd = i & 63;
        out[((size_t)b_ * LL + l) * DM + h * HD + dd] = tile[i];
    }
}

// K5: add exclusive prefix of segment totals.
__global__ __launch_bounds__(256) void k_cumsum_off(float* __restrict__ out) {
    int seg = blockIdx.x, bh = blockIdx.y, tid = threadIdx.x;
    if (seg == 0) return;
    __shared__ float offs[HD];
    if (tid < HD) {
        float s = 0.f;
        for (int ss = 0; ss < seg; ss++) s += g_seg[((size_t)bh * NSEG + ss) * HD + tid];
        offs[tid] = s;
    }
    __syncthreads();
    int b_ = bh >> 3, h = bh & 7;
    for (int i = tid; i < SEGL * HD; i += 256) {
        int l = seg * SEGL + (i >> 6), dd = i & 63;
        out[((size_t)b_ * LL + l) * DM + h * HD + dd] += offs[dd];
    }
}

// ---------------------------------------------------------------------------
// K6: scores[bh][u][j] = 0.125 * q_top[u] . k_j, masked -inf for j > m_top[u].
// Block = (key-chunk of 64, bh). Keys staged in padded SMEM (conflict-free),
// 45 queries staged in SMEM. Thread = (key, u-group of 4).
// ---------------------------------------------------------------------------
__global__ __launch_bounds__(256) void k_scores() {
    __shared__ float qs[SK * HD];
    __shared__ float ks[64 * 65];
    __shared__ int   tp[SK];
    int bh = blockIdx.y, tid = threadIdx.x;
    int j0 = blockIdx.x * 64;
    const float* Qb = g_Q + (size_t)bh * LL * HD;
    const float* Kb = g_K + (size_t)bh * LL * HD;
    if (tid < SK) tp[tid] = g_top[bh * SK + tid];
    __syncthreads();
    for (int i = tid; i < SK * HD; i += 256) {
        int u = i >> 6, dd = i & 63;
        qs[i] = Qb[(size_t)tp[u] * HD + dd];
    }
    for (int i = tid; i < 64 * HD; i += 256) {
        int jj = i >> 6, dd = i & 63;
        ks[jj * 65 + dd] = Kb[(size_t)(j0 + jj) * HD + dd];
    }
    __syncthreads();
    int key = tid & 63, ug = tid >> 6;
    int j = j0 + key;
    for (int u = ug; u < SK; u += 4) {
        float acc = 0.f;
        #pragma unroll 16
        for (int dd = 0; dd < HD; dd++) acc += qs[u * HD + dd] * ks[key * 65 + dd];
        float s = (j > tp[u]) ? -INFINITY : acc * 0.125f;
        g_sc[((size_t)bh * SK + u) * LL + j] = s;
    }
}

// K7: row softmax over 4096 keys (in place).
__global__ __launch_bounds__(256) void k_softmax() {
    __shared__ float red[256];
    int u = blockIdx.x, bh = blockIdx.y, tid = threadIdx.x;
    float* row = g_sc + ((size_t)bh * SK + u) * LL;
    float mx = -INFINITY;
    for (int i = tid; i < LL; i += 256) mx = fmaxf(mx, row[i]);
    red[tid] = mx; __syncthreads();
    for (int off = 128; off; off >>= 1) { if (tid < off) red[tid] = fmaxf(red[tid], red[tid + off]); __syncthreads(); }
    mx = red[0]; __syncthreads();
    float sm = 0.f;
    for (int i = tid; i < LL; i += 256) { float e = expf(row[i] - mx); row[i] = e; sm += e; }
    red[tid] = sm; __syncthreads();
    for (int off = 128; off; off >>= 1) { if (tid < off) red[tid] += red[tid + off]; __syncthreads(); }
    float inv = 1.f / red[0];
    for (int i = tid; i < LL; i += 256) row[i] *= inv;
}

// ---------------------------------------------------------------------------
// K8: upd partials: block = (j-segment of 256 keys, bh). acc[u][d] over its
// segment, V and prob chunks staged in SMEM. Thread = (d, u-group of 4).
// ---------------------------------------------------------------------------
__global__ __launch_bounds__(256) void k_updpart() {
    __shared__ float vs[32 * HD];
    __shared__ float ps[SK * 32];
    int jseg = blockIdx.x, bh = blockIdx.y, tid = threadIdx.x;
    const float* Vb = g_V + (size_t)bh * LL * HD;
    int d = tid & 63, ug = tid >> 6;
    float acc[12];
    #pragma unroll
    for (int c = 0; c < 12; c++) acc[c] = 0.f;
    for (int jc = jseg * 256; jc < (jseg + 1) * 256; jc += 32) {
        for (int i = tid; i < 32 * HD; i += 256) vs[i] = Vb[(size_t)jc * HD + i];
        for (int i = tid; i < SK * 32; i += 256) {
            int u = i >> 5, jj = i & 31;
            ps[i] = g_sc[((size_t)bh * SK + u) * LL + jc + jj];
        }
        __syncthreads();
        for (int jj = 0; jj < 32; jj++) {
            float vv = vs[jj * HD + d];
            int c = 0;
            for (int u = ug; u < SK; u += 4, c++) acc[c] += ps[u * 32 + jj] * vv;
        }
        __syncthreads();
    }
    int c = 0;
    for (int u = ug; u < SK; u += 4, c++)
        g_part[(((size_t)bh * JSEGS + jseg) * SK + u) * HD + d] = acc[c];
}

// K9: reduce partials and scatter into out at top rows (overwrites cumsum).
__global__ void k_scatter(float* __restrict__ out) {
    int u = blockIdx.x, bh = blockIdx.y, d = threadIdx.x;
    float s = 0.f;
    for (int seg = 0; seg < JSEGS; seg++)
        s += g_part[(((size_t)bh * JSEGS + seg) * SK + u) * HD + d];
    int b_ = bh >> 3, h = bh & 7, l = g_top[bh * SK + u];
    out[((size_t)b_ * LL + l) * DM + h * HD + d] = s;
}

// ---------------------------------------------------------------------------
extern "C" void kernel_launch(void* const* d_in, const int* in_sizes, int n_in,
                              void* d_out, int out_size) {
    const float* queries = (const float*)d_in[0];
    const float* keys    = (const float*)d_in[1];
    const float* values  = (const float*)d_in[2];
    const float* Wq = (const float*)d_in[3];
    const float* bq = (const float*)d_in[4];
    const float* Wk = (const float*)d_in[5];
    const float* bk = (const float*)d_in[6];
    const float* Wv = (const float*)d_in[7];
    const float* bv = (const float*)d_in[8];
    const int*   idx = (const int*)d_in[9];
    float* out = (float*)d_out;

    k_proj<<<dim3(DM / 128, BB * LL / 128, 3), 256>>>(queries, keys, values,
                                                      Wq, bq, Wk, bk, Wv, bv);
    k_mscore<<<dim3(LL / 8, BH), 256>>>(idx);
    k_topk<<<BH, 256>>>();
    k_cumsum_local<<<dim3(NSEG, BH), 256>>>(out);
    k_cumsum_off<<<dim3(NSEG, BH), 256>>>(out);
    k_scores<<<dim3(LL / 64, BH), 256>>>();
    k_softmax<<<dim3(SK, BH), 256>>>();
    k_updpart<<<dim3(JSEGS, BH), 256>>>();
    k_scatter<<<dim3(SK, BH), 64>>>(out);
}

// round 4
// speedup vs baseline: 1.5064x; 1.5064x over previous
#include <cuda_runtime.h>
#include <cuda_bf16.h>
#include <math.h>
#include <stdint.h>

// Problem constants (fixed shapes)
#define BB 2
#define LL 4096
#define DM 512
#define NH 8
#define HD 64
#define SK 45                 // sample_k = n_top = min(5*ceil(ln(4096)), 4096)
#define BH (BB*NH)
#define NSEG 32
#define SEGL (LL/NSEG)        // 128
#define JSEGS 16              // j-splits for upd partial sums

// Scratch (device globals — no allocation allowed in kernel_launch)
__device__ float g_Q[BB*NH*LL*HD];
__device__ float g_K[BB*NH*LL*HD];
__device__ float g_V[BB*NH*LL*HD];
__device__ float g_m[BH*LL];
__device__ int   g_top[BH*SK];
__device__ float g_seg[BH*NSEG*HD];
__device__ float g_sc[BH*SK*LL];
__device__ float g_part[BH*JSEGS*SK*HD];

// ===========================================================================
// tf32 helpers (legacy mma.sync path — compiles at compute_103 baseline)
// ===========================================================================
__device__ __forceinline__ uint32_t f32_to_tf32(float x) {
    uint32_t r;
    asm("cvt.rna.tf32.f32 %0, %1;" : "=r"(r) : "f"(x));
    return r;
}

// D += A(16x8,row) * B(8x8,col)  [tf32, fp32 accum]
__device__ __forceinline__ void mma_tf32(float c[4], uint32_t a0, uint32_t a1,
                                         uint32_t a2, uint32_t a3,
                                         uint32_t b0, uint32_t b1) {
    asm volatile(
        "mma.sync.aligned.m16n8k8.row.col.f32.tf32.tf32.f32 "
        "{%0,%1,%2,%3}, {%4,%5,%6,%7}, {%8,%9}, {%0,%1,%2,%3};"
        : "+f"(c[0]), "+f"(c[1]), "+f"(c[2]), "+f"(c[3])
        : "r"(a0), "r"(a1), "r"(a2), "r"(a3), "r"(b0), "r"(b1));
}

// ---------------------------------------------------------------------------
// K1: projection GEMM via 3xTF32 mma.sync. z selects q/k/v.
// C[128,128] tile per CTA; BK=32; 8 warps in 2(m) x 4(n); warp tile 64x32.
// Split: a = a_hi(tf32) + a_lo(tf32); products a0b0 + a1b0 + a0b1.
// SMEM: As hi/lo [32][136] u32, Bs hi/lo [32][136] u32 (stride 136 => the
// four k-offset groups land 8 banks apart: conflict-free fragment loads).
// Output head-transposed into g_{Q,K,V}[b][h][l][d], coalesced via staging.
// ---------------------------------------------------------------------------
#define KST 136               // padded row stride (floats) for smem tiles
#define AS0 0
#define AS1 (32*KST)          // 4352
#define BS0 (2*32*KST)        // 8704
#define BS1 (3*32*KST)        // 13056
#define PROJ_SMEM_BYTES (4*32*KST*4)   // 69632 B

__global__ __launch_bounds__(256, 2) void k_proj_mma(
    const float* __restrict__ Xq, const float* __restrict__ Xk, const float* __restrict__ Xv,
    const float* __restrict__ Wq, const float* __restrict__ bq,
    const float* __restrict__ Wk, const float* __restrict__ bk,
    const float* __restrict__ Wv, const float* __restrict__ bv)
{
    extern __shared__ uint32_t smem_u[];

    const float* A; const float* W; const float* bias; float* dst;
    if (blockIdx.z == 0)      { A = Xq; W = Wq; bias = bq; dst = g_Q; }
    else if (blockIdx.z == 1) { A = Xk; W = Wk; bias = bk; dst = g_K; }
    else                      { A = Xv; W = Wv; bias = bv; dst = g_V; }

    const int tid  = threadIdx.x;
    const int wid  = tid >> 5;
    const int lane = tid & 31;
    const int warp_m = wid >> 2;          // 0..1 (64 rows each)
    const int warp_n = wid & 3;           // 0..3 (32 cols each)
    const int m0 = blockIdx.y * 128;
    const int n0 = blockIdx.x * 128;

    float c[4][4][4];
    #pragma unroll
    for (int mt = 0; mt < 4; mt++)
        #pragma unroll
        for (int nt = 0; nt < 4; nt++)
            #pragma unroll
            for (int i = 0; i < 4; i++) c[mt][nt][i] = 0.f;

    const int fr = lane >> 2;             // fragment row/col helper: lane/4
    const int fk = lane & 3;              // lane%4

    for (int k0 = 0; k0 < DM; k0 += 32) {
        // ---- A chunk 128(m) x 32(k): load float4 along k, split, transpose ----
        #pragma unroll
        for (int t = 0; t < 4; t++) {
            int f = tid + t * 256;        // 0..1023 float4s
            int row = f >> 3;             // m 0..127
            int c4  = (f & 7) * 4;        // k offset
            float4 v = *(const float4*)&A[(size_t)(m0 + row) * DM + k0 + c4];
            float xs[4] = {v.x, v.y, v.z, v.w};
            #pragma unroll
            for (int j = 0; j < 4; j++) {
                uint32_t hi = f32_to_tf32(xs[j]);
                float res = xs[j] - __uint_as_float(hi);
                uint32_t lo = f32_to_tf32(res);
                smem_u[AS0 + (c4 + j) * KST + row] = hi;
                smem_u[AS1 + (c4 + j) * KST + row] = lo;
            }
        }
        // ---- B chunk 32(k) x 128(n): B[k][n] = W[k0+k][n0+n] ----
        #pragma unroll
        for (int t = 0; t < 4; t++) {
            int f = tid + t * 256;        // 0..1023 float4s
            int kk = f >> 5;              // k 0..31
            int c4 = (f & 31) * 4;        // n offset
            float4 v = *(const float4*)&W[(size_t)(k0 + kk) * DM + n0 + c4];
            float xs[4] = {v.x, v.y, v.z, v.w};
            #pragma unroll
            for (int j = 0; j < 4; j++) {
                uint32_t hi = f32_to_tf32(xs[j]);
                float res = xs[j] - __uint_as_float(hi);
                uint32_t lo = f32_to_tf32(res);
                smem_u[BS0 + kk * KST + c4 + j] = hi;
                smem_u[BS1 + kk * KST + c4 + j] = lo;
            }
        }
        __syncthreads();

        // ---- 3 products: (A_hi,B_hi), (A_lo,B_hi), (A_hi,B_lo) ----
        #pragma unroll
        for (int prod = 0; prod < 3; prod++) {
            const uint32_t* As = smem_u + (prod == 1 ? AS1 : AS0);
            const uint32_t* Bs = smem_u + (prod == 2 ? BS1 : BS0);
            #pragma unroll
            for (int ks = 0; ks < 4; ks++) {
                const int kb = ks * 8;
                uint32_t af[4][4];
                #pragma unroll
                for (int mt = 0; mt < 4; mt++) {
                    int mb = warp_m * 64 + mt * 16;
                    af[mt][0] = As[(kb + fk)     * KST + mb + fr];
                    af[mt][1] = As[(kb + fk)     * KST + mb + fr + 8];
                    af[mt][2] = As[(kb + fk + 4) * KST + mb + fr];
                    af[mt][3] = As[(kb + fk + 4) * KST + mb + fr + 8];
                }
                uint32_t bf[4][2];
                #pragma unroll
                for (int nt = 0; nt < 4; nt++) {
                    int nb = warp_n * 32 + nt * 8;
                    bf[nt][0] = Bs[(kb + fk)     * KST + nb + fr];
                    bf[nt][1] = Bs[(kb + fk + 4) * KST + nb + fr];
                }
                #pragma unroll
                for (int mt = 0; mt < 4; mt++)
                    #pragma unroll
                    for (int nt = 0; nt < 4; nt++)
                        mma_tf32(c[mt][nt], af[mt][0], af[mt][1], af[mt][2], af[mt][3],
                                 bf[nt][0], bf[nt][1]);
            }
        }
        __syncthreads();
    }

    // ---- epilogue: accum -> smem staging (row stride 132) -> coalesced store ----
    float* stg = (float*)smem_u;          // 128 x 132 floats = 67584 B (fits)
    #pragma unroll
    for (int mt = 0; mt < 4; mt++) {
        #pragma unroll
        for (int nt = 0; nt < 4; nt++) {
            int m = warp_m * 64 + mt * 16 + fr;
            int n = warp_n * 32 + nt * 8 + fk * 2;
            stg[m * 132 + n]           = c[mt][nt][0];
            stg[m * 132 + n + 1]       = c[mt][nt][1];
            stg[(m + 8) * 132 + n]     = c[mt][nt][2];
            stg[(m + 8) * 132 + n + 1] = c[mt][nt][3];
        }
    }
    __syncthreads();
    for (int i = tid; i < 128 * 128; i += 256) {
        int row = i >> 7, col = i & 127;
        int n = n0 + col;
        int h = n >> 6, dd = n & 63;
        int mi = m0 + row;
        int b_ = mi >> 12, l = mi & (LL - 1);
        dst[(((size_t)(b_ * NH + h) * LL) + l) * HD + dd] = stg[row * 132 + col] + bias[n];
    }
}

// ---------------------------------------------------------------------------
// K2: sparse measurement m[bh][l] = max_s(q_l . k_{idx[l,s]}) - sum_s(...)/L
// ---------------------------------------------------------------------------
__global__ __launch_bounds__(256) void k_mscore(const int* __restrict__ idx) {
    int bh = blockIdx.y;
    int w = threadIdx.x >> 5, lane = threadIdx.x & 31;
    int l = blockIdx.x * 8 + w;
    const float* Qb = g_Q + (size_t)bh * LL * HD;
    const float* Kb = g_K + (size_t)bh * LL * HD;
    float q0 = Qb[l * HD + lane];
    float q1 = Qb[l * HD + lane + 32];
    float mx = -INFINITY, sm = 0.f;
    for (int s = 0; s < SK; s++) {
        int j = idx[l * SK + s];
        float p = q0 * Kb[j * HD + lane] + q1 * Kb[j * HD + lane + 32];
        #pragma unroll
        for (int o = 16; o; o >>= 1) p += __shfl_xor_sync(0xffffffffu, p, o);
        mx = fmaxf(mx, p);
        sm += p;
    }
    if (lane == 0) g_m[bh * LL + l] = mx - sm * (1.f / LL);
}

// ---------------------------------------------------------------------------
// K3: top-45 of 4096 per (b,h). Iterative argmax, smaller-index tie-break.
// ---------------------------------------------------------------------------
__global__ __launch_bounds__(256) void k_topk() {
    __shared__ float sv[LL];
    __shared__ float rv[256];
    __shared__ int   ri[256];
    int bh = blockIdx.x, tid = threadIdx.x;
    for (int i = tid; i < LL; i += 256) sv[i] = g_m[bh * LL + i];
    __syncthreads();
    for (int t = 0; t < SK; t++) {
        float bv_ = -INFINITY; int bi = LL;
        for (int i = tid; i < LL; i += 256) {
            float v = sv[i];
            if (v > bv_) { bv_ = v; bi = i; }
        }
        rv[tid] = bv_; ri[tid] = bi;
        __syncthreads();
        for (int off = 128; off; off >>= 1) {
            if (tid < off) {
                float ov = rv[tid + off]; int oi = ri[tid + off];
                if (ov > rv[tid] || (ov == rv[tid] && oi < ri[tid])) { rv[tid] = ov; ri[tid] = oi; }
            }
            __syncthreads();
        }
        if (tid == 0) { g_top[bh * SK + t] = ri[0]; sv[ri[0]] = -INFINITY; }
        __syncthreads();
    }
}

// ---------------------------------------------------------------------------
// K4: segmented inclusive cumsum of V along seq (local part).
// ---------------------------------------------------------------------------
__global__ __launch_bounds__(256) void k_cumsum_local(float* __restrict__ out) {
    __shared__ float tile[SEGL * HD];
    int seg = blockIdx.x, bh = blockIdx.y, tid = threadIdx.x;
    const float* Vb = g_V + (size_t)bh * LL * HD + (size_t)seg * SEGL * HD;
    for (int i = tid; i < SEGL * HD; i += 256) tile[i] = Vb[i];
    __syncthreads();
    if (tid < HD) {
        float acc = tile[tid];
        for (int l = 1; l < SEGL; l++) { acc += tile[l * HD + tid]; tile[l * HD + tid] = acc; }
        g_seg[((size_t)bh * NSEG + seg) * HD + tid] = acc;
    }
    __syncthreads();
    int b_ = bh >> 3, h = bh & 7;
    for (int i = tid; i < SEGL * HD; i += 256) {
        int l = seg * SEGL + (i >> 6), dd = i & 63;
        out[((size_t)b_ * LL + l) * DM + h * HD + dd] = tile[i];
    }
}

// K5: add exclusive prefix of segment totals.
__global__ __launch_bounds__(256) void k_cumsum_off(float* __restrict__ out) {
    int seg = blockIdx.x, bh = blockIdx.y, tid = threadIdx.x;
    if (seg == 0) return;
    __shared__ float offs[HD];
    if (tid < HD) {
        float s = 0.f;
        for (int ss = 0; ss < seg; ss++) s += g_seg[((size_t)bh * NSEG + ss) * HD + tid];
        offs[tid] = s;
    }
    __syncthreads();
    int b_ = bh >> 3, h = bh & 7;
    for (int i = tid; i < SEGL * HD; i += 256) {
        int l = seg * SEGL + (i >> 6), dd = i & 63;
        out[((size_t)b_ * LL + l) * DM + h * HD + dd] += offs[dd];
    }
}

// ---------------------------------------------------------------------------
// K6: scores[bh][u][j] = 0.125 * q_top[u] . k_j, masked -inf for j > m_top[u].
// ---------------------------------------------------------------------------
__global__ __launch_bounds__(256) void k_scores() {
    __shared__ float qs[SK * HD];
    __shared__ float ks[64 * 65];
    __shared__ int   tp[SK];
    int bh = blockIdx.y, tid = threadIdx.x;
    int j0 = blockIdx.x * 64;
    const float* Qb = g_Q + (size_t)bh * LL * HD;
    const float* Kb = g_K + (size_t)bh * LL * HD;
    if (tid < SK) tp[tid] = g_top[bh * SK + tid];
    __syncthreads();
    for (int i = tid; i < SK * HD; i += 256) {
        int u = i >> 6, dd = i & 63;
        qs[i] = Qb[(size_t)tp[u] * HD + dd];
    }
    for (int i = tid; i < 64 * HD; i += 256) {
        int jj = i >> 6, dd = i & 63;
        ks[jj * 65 + dd] = Kb[(size_t)(j0 + jj) * HD + dd];
    }
    __syncthreads();
    int key = tid & 63, ug = tid >> 6;
    int j = j0 + key;
    for (int u = ug; u < SK; u += 4) {
        float acc = 0.f;
        #pragma unroll 16
        for (int dd = 0; dd < HD; dd++) acc += qs[u * HD + dd] * ks[key * 65 + dd];
        float s = (j > tp[u]) ? -INFINITY : acc * 0.125f;
        g_sc[((size_t)bh * SK + u) * LL + j] = s;
    }
}

// K7: row softmax over 4096 keys (in place).
__global__ __launch_bounds__(256) void k_softmax() {
    __shared__ float red[256];
    int u = blockIdx.x, bh = blockIdx.y, tid = threadIdx.x;
    float* row = g_sc + ((size_t)bh * SK + u) * LL;
    float mx = -INFINITY;
    for (int i = tid; i < LL; i += 256) mx = fmaxf(mx, row[i]);
    red[tid] = mx; __syncthreads();
    for (int off = 128; off; off >>= 1) { if (tid < off) red[tid] = fmaxf(red[tid], red[tid + off]); __syncthreads(); }
    mx = red[0]; __syncthreads();
    float sm = 0.f;
    for (int i = tid; i < LL; i += 256) { float e = expf(row[i] - mx); row[i] = e; sm += e; }
    red[tid] = sm; __syncthreads();
    for (int off = 128; off; off >>= 1) { if (tid < off) red[tid] += red[tid + off]; __syncthreads(); }
    float inv = 1.f / red[0];
    for (int i = tid; i < LL; i += 256) row[i] *= inv;
}

// ---------------------------------------------------------------------------
// K8: upd partials: block = (j-segment of 256 keys, bh).
// ---------------------------------------------------------------------------
__global__ __launch_bounds__(256) void k_updpart() {
    __shared__ float vs[32 * HD];
    __shared__ float ps[SK * 32];
    int jseg = blockIdx.x, bh = blockIdx.y, tid = threadIdx.x;
    const float* Vb = g_V + (size_t)bh * LL * HD;
    int d = tid & 63, ug = tid >> 6;
    float acc[12];
    #pragma unroll
    for (int c = 0; c < 12; c++) acc[c] = 0.f;
    for (int jc = jseg * 256; jc < (jseg + 1) * 256; jc += 32) {
        for (int i = tid; i < 32 * HD; i += 256) vs[i] = Vb[(size_t)jc * HD + i];
        for (int i = tid; i < SK * 32; i += 256) {
            int u = i >> 5, jj = i & 31;
            ps[i] = g_sc[((size_t)bh * SK + u) * LL + jc + jj];
        }
        __syncthreads();
        for (int jj = 0; jj < 32; jj++) {
            float vv = vs[jj * HD + d];
            int c = 0;
            for (int u = ug; u < SK; u += 4, c++) acc[c] += ps[u * 32 + jj] * vv;
        }
        __syncthreads();
    }
    int c = 0;
    for (int u = ug; u < SK; u += 4, c++)
        g_part[(((size_t)bh * JSEGS + jseg) * SK + u) * HD + d] = acc[c];
}

// K9: reduce partials and scatter into out at top rows (overwrites cumsum).
__global__ void k_scatter(float* __restrict__ out) {
    int u = blockIdx.x, bh = blockIdx.y, d = threadIdx.x;
    float s = 0.f;
    for (int seg = 0; seg < JSEGS; seg++)
        s += g_part[(((size_t)bh * JSEGS + seg) * SK + u) * HD + d];
    int b_ = bh >> 3, h = bh & 7, l = g_top[bh * SK + u];
    out[((size_t)b_ * LL + l) * DM + h * HD + d] = s;
}

// ---------------------------------------------------------------------------
extern "C" void kernel_launch(void* const* d_in, const int* in_sizes, int n_in,
                              void* d_out, int out_size) {
    const float* queries = (const float*)d_in[0];
    const float* keys    = (const float*)d_in[1];
    const float* values  = (const float*)d_in[2];
    const float* Wq = (const float*)d_in[3];
    const float* bq = (const float*)d_in[4];
    const float* Wk = (const float*)d_in[5];
    const float* bk = (const float*)d_in[6];
    const float* Wv = (const float*)d_in[7];
    const float* bv = (const float*)d_in[8];
    const int*   idx = (const int*)d_in[9];
    float* out = (float*)d_out;

    cudaFuncSetAttribute(k_proj_mma, cudaFuncAttributeMaxDynamicSharedMemorySize,
                         PROJ_SMEM_BYTES);

    k_proj_mma<<<dim3(DM / 128, BB * LL / 128, 3), 256, PROJ_SMEM_BYTES>>>(
        queries, keys, values, Wq, bq, Wk, bk, Wv, bv);
    k_mscore<<<dim3(LL / 8, BH), 256>>>(idx);
    k_topk<<<BH, 256>>>();
    k_cumsum_local<<<dim3(NSEG, BH), 256>>>(out);
    k_cumsum_off<<<dim3(NSEG, BH), 256>>>(out);
    k_scores<<<dim3(LL / 64, BH), 256>>>();
    k_softmax<<<dim3(SK, BH), 256>>>();
    k_updpart<<<dim3(JSEGS, BH), 256>>>();
    k_scatter<<<dim3(SK, BH), 64>>>(out);
}

// round 8
// speedup vs baseline: 1.7429x; 1.1570x over previous
#include <cuda_runtime.h>
#include <cuda_bf16.h>
#include <math.h>
#include <stdint.h>

// Problem constants (fixed shapes)
#define BB 2
#define LL 4096
#define DM 512
#define NH 8
#define HD 64
#define SK 45                 // sample_k = n_top = min(5*ceil(ln(4096)), 4096)
#define BH (BB*NH)
#define NSEG 32
#define SEGL (LL/NSEG)        // 128
#define JSEGS 16              // j-splits for upd partial sums
#define MM (BB*LL)            // 8192 rows

// Scratch (device globals — no allocation allowed in kernel_launch)
__device__ float g_Q[BB*NH*LL*HD];
__device__ float g_K[BB*NH*LL*HD];
__device__ float g_V[BB*NH*LL*HD];
__device__ float g_m[BH*LL];
__device__ int   g_top[BH*SK];
__device__ float g_seg[BH*NSEG*HD];
__device__ float g_sc[BH*SK*LL];
__device__ float g_part[BH*JSEGS*SK*HD];
// tf32 split scratch
__device__ uint32_t g_Ah[3u*MM*DM];
__device__ uint32_t g_Al[3u*MM*DM];
__device__ uint32_t g_Wh[3u*DM*DM];   // transposed: [n][k]
__device__ uint32_t g_Wl[3u*DM*DM];

// ===========================================================================
// tf32 / mma helpers (legacy mma.sync path — compiles at compute_103 baseline)
// ===========================================================================
__device__ __forceinline__ uint32_t f32_to_tf32(float x) {
    uint32_t r;
    asm("cvt.rna.tf32.f32 %0, %1;" : "=r"(r) : "f"(x));
    return r;
}
__device__ __forceinline__ void mma_tf32(float c[4], uint32_t a0, uint32_t a1,
                                         uint32_t a2, uint32_t a3,
                                         uint32_t b0, uint32_t b1) {
    asm volatile(
        "mma.sync.aligned.m16n8k8.row.col.f32.tf32.tf32.f32 "
        "{%0,%1,%2,%3}, {%4,%5,%6,%7}, {%8,%9}, {%0,%1,%2,%3};"
        : "+f"(c[0]), "+f"(c[1]), "+f"(c[2]), "+f"(c[3])
        : "r"(a0), "r"(a1), "r"(a2), "r"(a3), "r"(b0), "r"(b1));
}
__device__ __forceinline__ uint32_t smem_addr_u32(const void* p) {
    uint32_t a;
    asm("{ .reg .u64 t; cvta.to.shared.u64 t, %1; cvt.u32.u64 %0, t; }" : "=r"(a) : "l"(p));
    return a;
}
#define CP_ASYNC16(dst, src) \
    asm volatile("cp.async.cg.shared.global [%0], [%1], 16;" :: "r"(dst), "l"(src))
#define CP_COMMIT() asm volatile("cp.async.commit_group;" ::: "memory")
#define CP_WAIT(n)  asm volatile("cp.async.wait_group %0;" :: "n"(n) : "memory")
#define LDSM_X4(r0, r1, r2, r3, addr) \
    asm volatile("ldmatrix.sync.aligned.m8n8.x4.shared.b16 {%0,%1,%2,%3}, [%4];" \
                 : "=r"(r0), "=r"(r1), "=r"(r2), "=r"(r3) : "r"(addr))

// ---------------------------------------------------------------------------
// K0a: elementwise tf32 hi/lo split of the three input matrices (coalesced).
// ---------------------------------------------------------------------------
__global__ __launch_bounds__(256) void k_splitX(
    const float* __restrict__ X0, const float* __restrict__ X1, const float* __restrict__ X2)
{
    int z = blockIdx.y;
    const float* X = (z == 0) ? X0 : (z == 1) ? X1 : X2;
    size_t i = (size_t)blockIdx.x * 256 + threadIdx.x;      // float4 index; 1M total
    float4 v = ((const float4*)X)[i];
    float xs[4] = {v.x, v.y, v.z, v.w};
    uint4 hi, lo;
    uint32_t* hp = (uint32_t*)&hi; uint32_t* lp = (uint32_t*)&lo;
    #pragma unroll
    for (int j = 0; j < 4; j++) {
        uint32_t h = f32_to_tf32(xs[j]);
        hp[j] = h;
        lp[j] = f32_to_tf32(xs[j] - __uint_as_float(h));
    }
    size_t base = (size_t)z * MM * DM / 4;
    ((uint4*)g_Ah)[base + i] = hi;
    ((uint4*)g_Al)[base + i] = lo;
}

// ---------------------------------------------------------------------------
// K0b: W transpose + split: g_W{h,l}[z][n][k] = split(W[k][n]).
// ---------------------------------------------------------------------------
__global__ __launch_bounds__(256) void k_splitW(
    const float* __restrict__ W0, const float* __restrict__ W1, const float* __restrict__ W2)
{
    __shared__ float t[32][33];
    int z = blockIdx.z;
    const float* W = (z == 0) ? W0 : (z == 1) ? W1 : W2;
    int bx = blockIdx.x * 32;   // n tile
    int by = blockIdx.y * 32;   // k tile
    int tx = threadIdx.x, ty = threadIdx.y;   // (32, 8)
    #pragma unroll
    for (int r = ty; r < 32; r += 8)
        t[r][tx] = W[(size_t)(by + r) * DM + bx + tx];
    __syncthreads();
    size_t zoff = (size_t)z * DM * DM;
    #pragma unroll
    for (int r = ty; r < 32; r += 8) {
        float x = t[tx][r];                   // = W[by+tx][bx+r]
        uint32_t h = f32_to_tf32(x);
        uint32_t l = f32_to_tf32(x - __uint_as_float(h));
        g_Wh[zoff + (size_t)(bx + r) * DM + by + tx] = h;
        g_Wl[zoff + (size_t)(bx + r) * DM + by + tx] = l;
    }
}

// ---------------------------------------------------------------------------
// K1: projection GEMM, 3xTF32 mma.sync, cp.async double buffer + ldmatrix.
// CTA tile 128x128, BK=32, 8 warps 2(m)x4(n), warp tile 64x32.
// SMEM per stage: Ah, Al (128 m x 32 k), Bh, Bl (128 n x 32 k); row stride 36
// u32 (bank = 4*row + k mod 32 -> ldmatrix conflict-free). 2 stages = 147456B.
// ---------------------------------------------------------------------------
#define RST 36                       // row stride in u32
#define TILE_W (128 * RST)           // 4608 u32 per tile
#define STAGE_W (4 * TILE_W)         // 18432 u32 per stage
#define PROJ_SMEM_BYTES (2 * STAGE_W * 4)   // 147456 B

__device__ __forceinline__ void ld_stage(uint32_t smb,
    const uint32_t* __restrict__ Ah, const uint32_t* __restrict__ Al,
    const uint32_t* __restrict__ Bh, const uint32_t* __restrict__ Bl,
    int k0, int tid)
{
    #pragma unroll
    for (int t = 0; t < 4; t++) {
        int idx = tid + t * 256;             // 0..1023
        int row = idx >> 3;
        int ch  = (idx & 7) * 4;             // float offset in row
        uint32_t d = smb + (uint32_t)(row * RST + ch) * 4;
        size_t s = (size_t)row * DM + k0 + ch;
        CP_ASYNC16(d,                    Ah + s);
        CP_ASYNC16(d + TILE_W * 4,       Al + s);
        CP_ASYNC16(d + 2 * TILE_W * 4,   Bh + s);
        CP_ASYNC16(d + 3 * TILE_W * 4,   Bl + s);
    }
}

__global__ __launch_bounds__(256, 1) void k_proj_mma2(
    const float* __restrict__ bq, const float* __restrict__ bk, const float* __restrict__ bv)
{
    extern __shared__ uint32_t smem_u[];
    const int z = blockIdx.z;
    const float* bias = (z == 0) ? bq : (z == 1) ? bk : bv;
    float* dst = (z == 0) ? g_Q : (z == 1) ? g_K : g_V;

    const int tid  = threadIdx.x;
    const int wid  = tid >> 5;
    const int lane = tid & 31;
    const int warp_m = wid >> 2;             // 0..1
    const int warp_n = wid & 3;              // 0..3
    const int m0 = blockIdx.y * 128;
    const int n0 = blockIdx.x * 128;

    const uint32_t* Ah = g_Ah + (size_t)z * MM * DM + (size_t)m0 * DM;
    const uint32_t* Al = g_Al + (size_t)z * MM * DM + (size_t)m0 * DM;
    const uint32_t* Bh = g_Wh + (size_t)z * DM * DM + (size_t)n0 * DM;
    const uint32_t* Bl = g_Wl + (size_t)z * DM * DM + (size_t)n0 * DM;

    const uint32_t smb = smem_addr_u32(smem_u);

    float c[4][4][4];
    #pragma unroll
    for (int mt = 0; mt < 4; mt++)
        #pragma unroll
        for (int nt = 0; nt < 4; nt++)
            #pragma unroll
            for (int i = 0; i < 4; i++) c[mt][nt][i] = 0.f;

    // per-thread ldmatrix address components
    const int g  = lane >> 3;
    const int r8 = lane & 7;
    const int aRow = warp_m * 64 + r8 + (g & 1) * 8;   // + mt*16
    const int aCol = (g >> 1) * 4;                     // + kb
    const int bRow = warp_n * 32 + r8 + (g >> 1) * 8;  // + pair*16
    const int bCol = (g & 1) * 4;                      // + kb

    ld_stage(smb, Ah, Al, Bh, Bl, 0, tid);
    CP_COMMIT();

    const int NCHUNK = DM / 32;              // 16
    for (int ck = 0; ck < NCHUNK; ck++) {
        if (ck + 1 < NCHUNK) {
            ld_stage(smb + ((ck + 1) & 1) * STAGE_W * 4, Ah, Al, Bh, Bl, (ck + 1) * 32, tid);
            CP_COMMIT();
            CP_WAIT(1);
        } else {
            CP_WAIT(0);
        }
        __syncthreads();

        const uint32_t stage = smb + (ck & 1) * STAGE_W * 4;
        #pragma unroll
        for (int prod = 0; prod < 3; prod++) {
            const uint32_t aoff = stage + (prod == 1 ? TILE_W * 4 : 0);
            const uint32_t boff = stage + 2 * TILE_W * 4 + (prod == 2 ? TILE_W * 4 : 0);
            #pragma unroll
            for (int ks = 0; ks < 4; ks++) {
                const int kb = ks * 8;
                uint32_t af[4][4];
                #pragma unroll
                for (int mt = 0; mt < 4; mt++) {
                    uint32_t addr = aoff + (uint32_t)(((aRow + mt * 16) * RST) + aCol + kb) * 4;
                    LDSM_X4(af[mt][0], af[mt][1], af[mt][2], af[mt][3], addr);
                }
                uint32_t bf[4][2];
                #pragma unroll
                for (int pr = 0; pr < 2; pr++) {
                    uint32_t addr = boff + (uint32_t)(((bRow + pr * 16) * RST) + bCol + kb) * 4;
                    LDSM_X4(bf[pr * 2][0], bf[pr * 2][1], bf[pr * 2 + 1][0], bf[pr * 2 + 1][1], addr);
                }
                #pragma unroll
                for (int mt = 0; mt < 4; mt++)
                    #pragma unroll
                    for (int nt = 0; nt < 4; nt++)
                        mma_tf32(c[mt][nt], af[mt][0], af[mt][1], af[mt][2], af[mt][3],
                                 bf[nt][0], bf[nt][1]);
            }
        }
        __syncthreads();
    }

    // ---- epilogue: accum -> smem staging (stride 132) -> coalesced store ----
    float* stg = (float*)smem_u;             // 128 x 132 floats = 67584 B
    const int fr = lane >> 2, fk = lane & 3;
    #pragma unroll
    for (int mt = 0; mt < 4; mt++) {
        #pragma unroll
        for (int nt = 0; nt < 4; nt++) {
            int m = warp_m * 64 + mt * 16 + fr;
            int n = warp_n * 32 + nt * 8 + fk * 2;
            stg[m * 132 + n]           = c[mt][nt][0];
            stg[m * 132 + n + 1]       = c[mt][nt][1];
            stg[(m + 8) * 132 + n]     = c[mt][nt][2];
            stg[(m + 8) * 132 + n + 1] = c[mt][nt][3];
        }
    }
    __syncthreads();
    for (int i = tid; i < 128 * 128; i += 256) {
        int row = i >> 7, col = i & 127;
        int n = n0 + col;
        int h = n >> 6, dd = n & 63;
        int mi = m0 + row;
        int b_ = mi >> 12, l = mi & (LL - 1);
        dst[(((size_t)(b_ * NH + h) * LL) + l) * HD + dd] = stg[row * 132 + col] + bias[n];
    }
}

// ---------------------------------------------------------------------------
// K2: sparse measurement m[bh][l] = max_s(q_l . k_{idx[l,s]}) - sum_s(...)/L
// ---------------------------------------------------------------------------
__global__ __launch_bounds__(256) void k_mscore(const int* __restrict__ idx) {
    int bh = blockIdx.y;
    int w = threadIdx.x >> 5, lane = threadIdx.x & 31;
    int l = blockIdx.x * 8 + w;
    const float* Qb = g_Q + (size_t)bh * LL * HD;
    const float* Kb = g_K + (size_t)bh * LL * HD;
    float q0 = Qb[l * HD + lane];
    float q1 = Qb[l * HD + lane + 32];
    float mx = -INFINITY, sm = 0.f;
    for (int s = 0; s < SK; s++) {
        int j = idx[l * SK + s];
        float p = q0 * Kb[j * HD + lane] + q1 * Kb[j * HD + lane + 32];
        #pragma unroll
        for (int o = 16; o; o >>= 1) p += __shfl_xor_sync(0xffffffffu, p, o);
        mx = fmaxf(mx, p);
        sm += p;
    }
    if (lane == 0) g_m[bh * LL + l] = mx - sm * (1.f / LL);
}

// ---------------------------------------------------------------------------
// K3: top-45 of 4096 per (b,h). Iterative argmax, smaller-index tie-break.
// ---------------------------------------------------------------------------
__global__ __launch_bounds__(256) void k_topk() {
    __shared__ float sv[LL];
    __shared__ float rv[256];
    __shared__ int   ri[256];
    int bh = blockIdx.x, tid = threadIdx.x;
    for (int i = tid; i < LL; i += 256) sv[i] = g_m[bh * LL + i];
    __syncthreads();
    for (int t = 0; t < SK; t++) {
        float bv_ = -INFINITY; int bi = LL;
        for (int i = tid; i < LL; i += 256) {
            float v = sv[i];
            if (v > bv_) { bv_ = v; bi = i; }
        }
        rv[tid] = bv_; ri[tid] = bi;
        __syncthreads();
        for (int off = 128; off; off >>= 1) {
            if (tid < off) {
                float ov = rv[tid + off]; int oi = ri[tid + off];
                if (ov > rv[tid] || (ov == rv[tid] && oi < ri[tid])) { rv[tid] = ov; ri[tid] = oi; }
            }
            __syncthreads();
        }
        if (tid == 0) { g_top[bh * SK + t] = ri[0]; sv[ri[0]] = -INFINITY; }
        __syncthreads();
    }
}

// ---------------------------------------------------------------------------
// K4: segmented inclusive cumsum of V along seq (local part).
// ---------------------------------------------------------------------------
__global__ __launch_bounds__(256) void k_cumsum_local(float* __restrict__ out) {
    __shared__ float tile[SEGL * HD];
    int seg = blockIdx.x, bh = blockIdx.y, tid = threadIdx.x;
    const float* Vb = g_V + (size_t)bh * LL * HD + (size_t)seg * SEGL * HD;
    for (int i = tid; i < SEGL * HD; i += 256) tile[i] = Vb[i];
    __syncthreads();
    if (tid < HD) {
        float acc = tile[tid];
        for (int l = 1; l < SEGL; l++) { acc += tile[l * HD + tid]; tile[l * HD + tid] = acc; }
        g_seg[((size_t)bh * NSEG + seg) * HD + tid] = acc;
    }
    __syncthreads();
    int b_ = bh >> 3, h = bh & 7;
    for (int i = tid; i < SEGL * HD; i += 256) {
        int l = seg * SEGL + (i >> 6), dd = i & 63;
        out[((size_t)b_ * LL + l) * DM + h * HD + dd] = tile[i];
    }
}

// K5: add exclusive prefix of segment totals.
__global__ __launch_bounds__(256) void k_cumsum_off(float* __restrict__ out) {
    int seg = blockIdx.x, bh = blockIdx.y, tid = threadIdx.x;
    if (seg == 0) return;
    __shared__ float offs[HD];
    if (tid < HD) {
        float s = 0.f;
        for (int ss = 0; ss < seg; ss++) s += g_seg[((size_t)bh * NSEG + ss) * HD + tid];
        offs[tid] = s;
    }
    __syncthreads();
    int b_ = bh >> 3, h = bh & 7;
    for (int i = tid; i < SEGL * HD; i += 256) {
        int l = seg * SEGL + (i >> 6), dd = i & 63;
        out[((size_t)b_ * LL + l) * DM + h * HD + dd] += offs[dd];
    }
}

// ---------------------------------------------------------------------------
// K6: scores[bh][u][j] = 0.125 * q_top[u] . k_j, masked -inf for j > m_top[u].
// ---------------------------------------------------------------------------
__global__ __launch_bounds__(256) void k_scores() {
    __shared__ float qs[SK * HD];
    __shared__ float ks[64 * 65];
    __shared__ int   tp[SK];
    int bh = blockIdx.y, tid = threadIdx.x;
    int j0 = blockIdx.x * 64;
    const float* Qb = g_Q + (size_t)bh * LL * HD;
    const float* Kb = g_K + (size_t)bh * LL * HD;
    if (tid < SK) tp[tid] = g_top[bh * SK + tid];
    __syncthreads();
    for (int i = tid; i < SK * HD; i += 256) {
        int u = i >> 6, dd = i & 63;
        qs[i] = Qb[(size_t)tp[u] * HD + dd];
    }
    for (int i = tid; i < 64 * HD; i += 256) {
        int jj = i >> 6, dd = i & 63;
        ks[jj * 65 + dd] = Kb[(size_t)(j0 + jj) * HD + dd];
    }
    __syncthreads();
    int key = tid & 63, ug = tid >> 6;
    int j = j0 + key;
    for (int u = ug; u < SK; u += 4) {
        float acc = 0.f;
        #pragma unroll 16
        for (int dd = 0; dd < HD; dd++) acc += qs[u * HD + dd] * ks[key * 65 + dd];
        float s = (j > tp[u]) ? -INFINITY : acc * 0.125f;
        g_sc[((size_t)bh * SK + u) * LL + j] = s;
    }
}

// K7: row softmax over 4096 keys (in place).
__global__ __launch_bounds__(256) void k_softmax() {
    __shared__ float red[256];
    int u = blockIdx.x, bh = blockIdx.y, tid = threadIdx.x;
    float* row = g_sc + ((size_t)bh * SK + u) * LL;
    float mx = -INFINITY;
    for (int i = tid; i < LL; i += 256) mx = fmaxf(mx, row[i]);
    red[tid] = mx; __syncthreads();
    for (int off = 128; off; off >>= 1) { if (tid < off) red[tid] = fmaxf(red[tid], red[tid + off]); __syncthreads(); }
    mx = red[0]; __syncthreads();
    float sm = 0.f;
    for (int i = tid; i < LL; i += 256) { float e = expf(row[i] - mx); row[i] = e; sm += e; }
    red[tid] = sm; __syncthreads();
    for (int off = 128; off; off >>= 1) { if (tid < off) red[tid] += red[tid + off]; __syncthreads(); }
    float inv = 1.f / red[0];
    for (int i = tid; i < LL; i += 256) row[i] *= inv;
}

// ---------------------------------------------------------------------------
// K8: upd partials: block = (j-segment of 256 keys, bh).
// ---------------------------------------------------------------------------
__global__ __launch_bounds__(256) void k_updpart() {
    __shared__ float vs[32 * HD];
    __shared__ float ps[SK * 32];
    int jseg = blockIdx.x, bh = blockIdx.y, tid = threadIdx.x;
    const float* Vb = g_V + (size_t)bh * LL * HD;
    int d = tid & 63, ug = tid >> 6;
    float acc[12];
    #pragma unroll
    for (int c = 0; c < 12; c++) acc[c] = 0.f;
    for (int jc = jseg * 256; jc < (jseg + 1) * 256; jc += 32) {
        for (int i = tid; i < 32 * HD; i += 256) vs[i] = Vb[(size_t)jc * HD + i];
        for (int i = tid; i < SK * 32; i += 256) {
            int u = i >> 5, jj = i & 31;
            ps[i] = g_sc[((size_t)bh * SK + u) * LL + jc + jj];
        }
        __syncthreads();
        for (int jj = 0; jj < 32; jj++) {
            float vv = vs[jj * HD + d];
            int c = 0;
            for (int u = ug; u < SK; u += 4, c++) acc[c] += ps[u * 32 + jj] * vv;
        }
        __syncthreads();
    }
    int c = 0;
    for (int u = ug; u < SK; u += 4, c++)
        g_part[(((size_t)bh * JSEGS + jseg) * SK + u) * HD + d] = acc[c];
}

// K9: reduce partials and scatter into out at top rows (overwrites cumsum).
__global__ void k_scatter(float* __restrict__ out) {
    int u = blockIdx.x, bh = blockIdx.y, d = threadIdx.x;
    float s = 0.f;
    for (int seg = 0; seg < JSEGS; seg++)
        s += g_part[(((size_t)bh * JSEGS + seg) * SK + u) * HD + d];
    int b_ = bh >> 3, h = bh & 7, l = g_top[bh * SK + u];
    out[((size_t)b_ * LL + l) * DM + h * HD + d] = s;
}

// ---------------------------------------------------------------------------
extern "C" void kernel_launch(void* const* d_in, const int* in_sizes, int n_in,
                              void* d_out, int out_size) {
    const float* queries = (const float*)d_in[0];
    const float* keys    = (const float*)d_in[1];
    const float* values  = (const float*)d_in[2];
    const float* Wq = (const float*)d_in[3];
    const float* bq = (const float*)d_in[4];
    const float* Wk = (const float*)d_in[5];
    const float* bk = (const float*)d_in[6];
    const float* Wv = (const float*)d_in[7];
    const float* bv = (const float*)d_in[8];
    const int*   idx = (const int*)d_in[9];
    float* out = (float*)d_out;

    cudaFuncSetAttribute(k_proj_mma2, cudaFuncAttributeMaxDynamicSharedMemorySize,
                         PROJ_SMEM_BYTES);

    k_splitX<<<dim3(MM * DM / 4 / 256, 3), 256>>>(queries, keys, values);
    k_splitW<<<dim3(16, 16, 3), dim3(32, 8)>>>(Wq, Wk, Wv);
    k_proj_mma2<<<dim3(DM / 128, MM / 128, 3), 256, PROJ_SMEM_BYTES>>>(bq, bk, bv);
    k_mscore<<<dim3(LL / 8, BH), 256>>>(idx);
    k_topk<<<BH, 256>>>();
    k_cumsum_local<<<dim3(NSEG, BH), 256>>>(out);
    k_cumsum_off<<<dim3(NSEG, BH), 256>>>(out);
    k_scores<<<dim3(LL / 64, BH), 256>>>();
    k_softmax<<<dim3(SK, BH), 256>>>();
    k_updpart<<<dim3(JSEGS, BH), 256>>>();
    k_scatter<<<dim3(SK, BH), 64>>>(out);
}

// round 9
// speedup vs baseline: 1.9570x; 1.1229x over previous
#include <cuda_runtime.h>
#include <cuda_bf16.h>
#include <math.h>
#include <stdint.h>

// Problem constants (fixed shapes)
#define BB 2
#define LL 4096
#define DM 512
#define NH 8
#define HD 64
#define SK 45                 // sample_k = n_top = min(5*ceil(ln(4096)), 4096)
#define BH (BB*NH)
#define NSEG 32
#define SEGL (LL/NSEG)        // 128
#define JSEGS 16              // j-splits for upd partial sums
#define MM (BB*LL)            // 8192 rows

// Scratch (device globals — no allocation allowed in kernel_launch)
__device__ float g_Q[BB*NH*LL*HD];
__device__ float g_K[BB*NH*LL*HD];
__device__ float g_V[BB*NH*LL*HD];
__device__ float g_m[BH*LL];
__device__ int   g_top[BH*SK];
__device__ float g_seg[BH*NSEG*HD];
__device__ float g_sc[BH*SK*LL];
__device__ float g_part[BH*JSEGS*SK*HD];
__device__ float g_rowsum[BH*SK];
// tf32 split scratch
__device__ uint32_t g_Ah[3u*MM*DM];
__device__ uint32_t g_Al[3u*MM*DM];
__device__ uint32_t g_Wh[3u*DM*DM];   // transposed: [n][k]
__device__ uint32_t g_Wl[3u*DM*DM];

// ===========================================================================
// tf32 / mma helpers (legacy mma.sync path — compiles at compute_103 baseline)
// ===========================================================================
__device__ __forceinline__ uint32_t f32_to_tf32(float x) {
    uint32_t r;
    asm("cvt.rna.tf32.f32 %0, %1;" : "=r"(r) : "f"(x));
    return r;
}
__device__ __forceinline__ void mma_tf32(float c[4], uint32_t a0, uint32_t a1,
                                         uint32_t a2, uint32_t a3,
                                         uint32_t b0, uint32_t b1) {
    asm volatile(
        "mma.sync.aligned.m16n8k8.row.col.f32.tf32.tf32.f32 "
        "{%0,%1,%2,%3}, {%4,%5,%6,%7}, {%8,%9}, {%0,%1,%2,%3};"
        : "+f"(c[0]), "+f"(c[1]), "+f"(c[2]), "+f"(c[3])
        : "r"(a0), "r"(a1), "r"(a2), "r"(a3), "r"(b0), "r"(b1));
}
__device__ __forceinline__ uint32_t smem_addr_u32(const void* p) {
    uint32_t a;
    asm("{ .reg .u64 t; cvta.to.shared.u64 t, %1; cvt.u32.u64 %0, t; }" : "=r"(a) : "l"(p));
    return a;
}
#define CP_ASYNC16(dst, src) \
    asm volatile("cp.async.cg.shared.global [%0], [%1], 16;" :: "r"(dst), "l"(src))
#define CP_COMMIT() asm volatile("cp.async.commit_group;" ::: "memory")
#define CP_WAIT(n)  asm volatile("cp.async.wait_group %0;" :: "n"(n) : "memory")
#define LDSM_X4(r0, r1, r2, r3, addr) \
    asm volatile("ldmatrix.sync.aligned.m8n8.x4.shared.b16 {%0,%1,%2,%3}, [%4];" \
                 : "=r"(r0), "=r"(r1), "=r"(r2), "=r"(r3) : "r"(addr))

// ---------------------------------------------------------------------------
// K0a: elementwise tf32 hi/lo split of the three input matrices (coalesced).
// ---------------------------------------------------------------------------
__global__ __launch_bounds__(256) void k_splitX(
    const float* __restrict__ X0, const float* __restrict__ X1, const float* __restrict__ X2)
{
    int z = blockIdx.y;
    const float* X = (z == 0) ? X0 : (z == 1) ? X1 : X2;
    size_t i = (size_t)blockIdx.x * 256 + threadIdx.x;      // float4 index; 1M total
    float4 v = ((const float4*)X)[i];
    float xs[4] = {v.x, v.y, v.z, v.w};
    uint4 hi, lo;
    uint32_t* hp = (uint32_t*)&hi; uint32_t* lp = (uint32_t*)&lo;
    #pragma unroll
    for (int j = 0; j < 4; j++) {
        uint32_t h = f32_to_tf32(xs[j]);
        hp[j] = h;
        lp[j] = f32_to_tf32(xs[j] - __uint_as_float(h));
    }
    size_t base = (size_t)z * MM * DM / 4;
    ((uint4*)g_Ah)[base + i] = hi;
    ((uint4*)g_Al)[base + i] = lo;
}

// ---------------------------------------------------------------------------
// K0b: W transpose + split: g_W{h,l}[z][n][k] = split(W[k][n]).
// ---------------------------------------------------------------------------
__global__ __launch_bounds__(256) void k_splitW(
    const float* __restrict__ W0, const float* __restrict__ W1, const float* __restrict__ W2)
{
    __shared__ float t[32][33];
    int z = blockIdx.z;
    const float* W = (z == 0) ? W0 : (z == 1) ? W1 : W2;
    int bx = blockIdx.x * 32;   // n tile
    int by = blockIdx.y * 32;   // k tile
    int tx = threadIdx.x, ty = threadIdx.y;   // (32, 8)
    #pragma unroll
    for (int r = ty; r < 32; r += 8)
        t[r][tx] = W[(size_t)(by + r) * DM + bx + tx];
    __syncthreads();
    size_t zoff = (size_t)z * DM * DM;
    #pragma unroll
    for (int r = ty; r < 32; r += 8) {
        float x = t[tx][r];                   // = W[by+tx][bx+r]
        uint32_t h = f32_to_tf32(x);
        uint32_t l = f32_to_tf32(x - __uint_as_float(h));
        g_Wh[zoff + (size_t)(bx + r) * DM + by + tx] = h;
        g_Wl[zoff + (size_t)(bx + r) * DM + by + tx] = l;
    }
}

// ---------------------------------------------------------------------------
// K1: projection GEMM, 3xTF32 mma.sync, cp.async double buffer + ldmatrix.
// CTA tile 128x128, BK=32, 8 warps 2(m)x4(n), warp tile 64x32.
// ---------------------------------------------------------------------------
#define RST 36                       // row stride in u32
#define TILE_W (128 * RST)           // 4608 u32 per tile
#define STAGE_W (4 * TILE_W)         // 18432 u32 per stage
#define PROJ_SMEM_BYTES (2 * STAGE_W * 4)   // 147456 B

__device__ __forceinline__ void ld_stage(uint32_t smb,
    const uint32_t* __restrict__ Ah, const uint32_t* __restrict__ Al,
    const uint32_t* __restrict__ Bh, const uint32_t* __restrict__ Bl,
    int k0, int tid)
{
    #pragma unroll
    for (int t = 0; t < 4; t++) {
        int idx = tid + t * 256;             // 0..1023
        int row = idx >> 3;
        int ch  = (idx & 7) * 4;             // float offset in row
        uint32_t d = smb + (uint32_t)(row * RST + ch) * 4;
        size_t s = (size_t)row * DM + k0 + ch;
        CP_ASYNC16(d,                    Ah + s);
        CP_ASYNC16(d + TILE_W * 4,       Al + s);
        CP_ASYNC16(d + 2 * TILE_W * 4,   Bh + s);
        CP_ASYNC16(d + 3 * TILE_W * 4,   Bl + s);
    }
}

__global__ __launch_bounds__(256, 1) void k_proj_mma2(
    const float* __restrict__ bq, const float* __restrict__ bk, const float* __restrict__ bv)
{
    extern __shared__ uint32_t smem_u[];
    const int z = blockIdx.z;
    const float* bias = (z == 0) ? bq : (z == 1) ? bk : bv;
    float* dst = (z == 0) ? g_Q : (z == 1) ? g_K : g_V;

    const int tid  = threadIdx.x;
    const int wid  = tid >> 5;
    const int lane = tid & 31;
    const int warp_m = wid >> 2;             // 0..1
    const int warp_n = wid & 3;              // 0..3
    const int m0 = blockIdx.y * 128;
    const int n0 = blockIdx.x * 128;

    const uint32_t* Ah = g_Ah + (size_t)z * MM * DM + (size_t)m0 * DM;
    const uint32_t* Al = g_Al + (size_t)z * MM * DM + (size_t)m0 * DM;
    const uint32_t* Bh = g_Wh + (size_t)z * DM * DM + (size_t)n0 * DM;
    const uint32_t* Bl = g_Wl + (size_t)z * DM * DM + (size_t)n0 * DM;

    const uint32_t smb = smem_addr_u32(smem_u);

    float c[4][4][4];
    #pragma unroll
    for (int mt = 0; mt < 4; mt++)
        #pragma unroll
        for (int nt = 0; nt < 4; nt++)
            #pragma unroll
            for (int i = 0; i < 4; i++) c[mt][nt][i] = 0.f;

    const int g  = lane >> 3;
    const int r8 = lane & 7;
    const int aRow = warp_m * 64 + r8 + (g & 1) * 8;
    const int aCol = (g >> 1) * 4;
    const int bRow = warp_n * 32 + r8 + (g >> 1) * 8;
    const int bCol = (g & 1) * 4;

    ld_stage(smb, Ah, Al, Bh, Bl, 0, tid);
    CP_COMMIT();

    const int NCHUNK = DM / 32;              // 16
    for (int ck = 0; ck < NCHUNK; ck++) {
        if (ck + 1 < NCHUNK) {
            ld_stage(smb + ((ck + 1) & 1) * STAGE_W * 4, Ah, Al, Bh, Bl, (ck + 1) * 32, tid);
            CP_COMMIT();
            CP_WAIT(1);
        } else {
            CP_WAIT(0);
        }
        __syncthreads();

        const uint32_t stage = smb + (ck & 1) * STAGE_W * 4;
        #pragma unroll
        for (int prod = 0; prod < 3; prod++) {
            const uint32_t aoff = stage + (prod == 1 ? TILE_W * 4 : 0);
            const uint32_t boff = stage + 2 * TILE_W * 4 + (prod == 2 ? TILE_W * 4 : 0);
            #pragma unroll
            for (int ks = 0; ks < 4; ks++) {
                const int kb = ks * 8;
                uint32_t af[4][4];
                #pragma unroll
                for (int mt = 0; mt < 4; mt++) {
                    uint32_t addr = aoff + (uint32_t)(((aRow + mt * 16) * RST) + aCol + kb) * 4;
                    LDSM_X4(af[mt][0], af[mt][1], af[mt][2], af[mt][3], addr);
                }
                uint32_t bf[4][2];
                #pragma unroll
                for (int pr = 0; pr < 2; pr++) {
                    uint32_t addr = boff + (uint32_t)(((bRow + pr * 16) * RST) + bCol + kb) * 4;
                    LDSM_X4(bf[pr * 2][0], bf[pr * 2][1], bf[pr * 2 + 1][0], bf[pr * 2 + 1][1], addr);
                }
                #pragma unroll
                for (int mt = 0; mt < 4; mt++)
                    #pragma unroll
                    for (int nt = 0; nt < 4; nt++)
                        mma_tf32(c[mt][nt], af[mt][0], af[mt][1], af[mt][2], af[mt][3],
                                 bf[nt][0], bf[nt][1]);
            }
        }
        __syncthreads();
    }

    // ---- epilogue: accum -> smem staging (stride 132) -> coalesced store ----
    float* stg = (float*)smem_u;             // 128 x 132 floats = 67584 B
    const int fr = lane >> 2, fk = lane & 3;
    #pragma unroll
    for (int mt = 0; mt < 4; mt++) {
        #pragma unroll
        for (int nt = 0; nt < 4; nt++) {
            int m = warp_m * 64 + mt * 16 + fr;
            int n = warp_n * 32 + nt * 8 + fk * 2;
            stg[m * 132 + n]           = c[mt][nt][0];
            stg[m * 132 + n + 1]       = c[mt][nt][1];
            stg[(m + 8) * 132 + n]     = c[mt][nt][2];
            stg[(m + 8) * 132 + n + 1] = c[mt][nt][3];
        }
    }
    __syncthreads();
    for (int i = tid; i < 128 * 128; i += 256) {
        int row = i >> 7, col = i & 127;
        int n = n0 + col;
        int h = n >> 6, dd = n & 63;
        int mi = m0 + row;
        int b_ = mi >> 12, l = mi & (LL - 1);
        dst[(((size_t)(b_ * NH + h) * LL) + l) * HD + dd] = stg[row * 132 + col] + bias[n];
    }
}

// ---------------------------------------------------------------------------
// K2: m[bh][l] = max_s(q_l . k_{idx[l,s]}) - sum_s(...)/L
// 8 lanes per row, 4 rows per warp, float4 loads, idx prefetched to smem.
// ---------------------------------------------------------------------------
__global__ __launch_bounds__(256) void k_mscore(const int* __restrict__ idx) {
    __shared__ int sidx[32 * SK];            // 32 rows' samples (contiguous in gmem)
    int bh = blockIdx.y;
    int l0 = blockIdx.x * 32;
    int tid = threadIdx.x;
    for (int i = tid; i < 32 * SK; i += 256) sidx[i] = idx[l0 * SK + i];
    __syncthreads();

    int wid = tid >> 5, lane = tid & 31;
    int grp = lane >> 3, sub = lane & 7;
    int lrel = wid * 4 + grp;
    int l = l0 + lrel;
    const float* Qb = g_Q + (size_t)bh * LL * HD;
    const float* Kb = g_K + (size_t)bh * LL * HD;
    float4 q0 = *(const float4*)&Qb[(size_t)l * HD + sub * 8];
    float4 q1 = *(const float4*)&Qb[(size_t)l * HD + sub * 8 + 4];
    const int* myidx = &sidx[lrel * SK];
    float mx = -INFINITY, sm = 0.f;
    #pragma unroll 3
    for (int s = 0; s < SK; s++) {
        int j = myidx[s];
        const float* kr = &Kb[(size_t)j * HD + sub * 8];
        float4 k0 = *(const float4*)kr;
        float4 k1 = *(const float4*)(kr + 4);
        float p = q0.x*k0.x + q0.y*k0.y + q0.z*k0.z + q0.w*k0.w
                + q1.x*k1.x + q1.y*k1.y + q1.z*k1.z + q1.w*k1.w;
        p += __shfl_xor_sync(0xffffffffu, p, 4);
        p += __shfl_xor_sync(0xffffffffu, p, 2);
        p += __shfl_xor_sync(0xffffffffu, p, 1);
        mx = fmaxf(mx, p);
        sm += p;
    }
    if (sub == 0) g_m[bh * LL + l] = mx - sm * (1.f / LL);
}

// ---------------------------------------------------------------------------
// K3: top-45 of 4096 per (b,h) via 4-pass radix threshold select.
// Order of the 45 outputs is arbitrary (downstream is keyed by the index
// value itself); tie-break among threshold-equal keys = smallest indices,
// matching jax.lax.top_k's selected SET exactly. Also zeroes g_rowsum.
// ---------------------------------------------------------------------------
__global__ __launch_bounds__(256) void k_topk() {
    __shared__ uint32_t keys[LL];            // 16 KB
    __shared__ uint32_t hist[256];
    __shared__ uint32_t s_prefix, s_need;
    __shared__ int s_cnt, s_eq;
    __shared__ int eq_list[256];
    int bh = blockIdx.x, tid = threadIdx.x;
    if (tid < SK) g_rowsum[bh * SK + tid] = 0.f;   // consumed by k_scores later
    for (int i = tid; i < LL; i += 256) {
        uint32_t u = __float_as_uint(g_m[bh * LL + i]);
        keys[i] = (u & 0x80000000u) ? ~u : (u | 0x80000000u);
    }
    if (tid == 0) { s_prefix = 0; s_need = SK; s_cnt = 0; s_eq = 0; }
    __syncthreads();

    for (int level = 0; level < 4; level++) {
        int shift = 24 - 8 * level;
        uint32_t pmask = (level == 0) ? 0u : (0xFFFFFFFFu << (shift + 8));
        hist[tid] = 0;
        __syncthreads();
        uint32_t prefix = s_prefix;
        for (int i = tid; i < LL; i += 256) {
            uint32_t u = keys[i];
            if ((u & pmask) == prefix) atomicAdd(&hist[(u >> shift) & 0xFFu], 1u);
        }
        __syncthreads();
        if (tid == 0) {
            uint32_t need = s_need, S = 0; int b;
            for (b = 255; b > 0; b--) {
                if (S + hist[b] >= need) break;
                S += hist[b];
            }
            s_prefix = prefix | ((uint32_t)b << shift);
            s_need = need - S;
        }
        __syncthreads();
    }
    uint32_t thresh = s_prefix;
    uint32_t need_eq = s_need;

    for (int i = tid; i < LL; i += 256) {
        uint32_t u = keys[i];
        if (u > thresh) {
            int p = atomicAdd(&s_cnt, 1);
            g_top[bh * SK + p] = i;
        } else if (u == thresh) {
            int p = atomicAdd(&s_eq, 1);
            if (p < 256) eq_list[p] = i;
        }
    }
    __syncthreads();
    if (tid == 0) {
        int E = s_eq < 256 ? s_eq : 256;
        int base = s_cnt;
        for (uint32_t t = 0; t < need_eq; t++) {
            int best = 1 << 30, bj = 0;
            for (int j2 = 0; j2 < E; j2++)
                if (eq_list[j2] < best) { best = eq_list[j2]; bj = j2; }
            g_top[bh * SK + base + t] = best;
            eq_list[bj] = 1 << 30;
        }
    }
}

// ---------------------------------------------------------------------------
// K4: segmented inclusive cumsum of V along seq (local part).
// ---------------------------------------------------------------------------
__global__ __launch_bounds__(256) void k_cumsum_local(float* __restrict__ out) {
    __shared__ float tile[SEGL * HD];
    int seg = blockIdx.x, bh = blockIdx.y, tid = threadIdx.x;
    const float* Vb = g_V + (size_t)bh * LL * HD + (size_t)seg * SEGL * HD;
    for (int i = tid; i < SEGL * HD; i += 256) tile[i] = Vb[i];
    __syncthreads();
    if (tid < HD) {
        float acc = tile[tid];
        for (int l = 1; l < SEGL; l++) { acc += tile[l * HD + tid]; tile[l * HD + tid] = acc; }
        g_seg[((size_t)bh * NSEG + seg) * HD + tid] = acc;
    }
    __syncthreads();
    int b_ = bh >> 3, h = bh & 7;
    for (int i = tid; i < SEGL * HD; i += 256) {
        int l = seg * SEGL + (i >> 6), dd = i & 63;
        out[((size_t)b_ * LL + l) * DM + h * HD + dd] = tile[i];
    }
}

// K5: add exclusive prefix of segment totals.
__global__ __launch_bounds__(256) void k_cumsum_off(float* __restrict__ out) {
    int seg = blockIdx.x, bh = blockIdx.y, tid = threadIdx.x;
    if (seg == 0) return;
    __shared__ float offs[HD];
    if (tid < HD) {
        float s = 0.f;
        for (int ss = 0; ss < seg; ss++) s += g_seg[((size_t)bh * NSEG + ss) * HD + tid];
        offs[tid] = s;
    }
    __syncthreads();
    int b_ = bh >> 3, h = bh & 7;
    for (int i = tid; i < SEGL * HD; i += 256) {
        int l = seg * SEGL + (i >> 6), dd = i & 63;
        out[((size_t)b_ * LL + l) * DM + h * HD + dd] += offs[dd];
    }
}

// ---------------------------------------------------------------------------
// K6: unnormalized attention weights: e = exp(0.125 * q_top[u] . k_j) for
// j <= tp[u], else 0. Accumulates per-(bh,u) row sums into g_rowsum.
// (scores bounded ~|s|<3 for this data => exp safe without max-subtract;
// softmax normalization happens in k_scatter.)
// ---------------------------------------------------------------------------
__global__ __launch_bounds__(256) void k_scores() {
    __shared__ float qs[SK * HD];
    __shared__ float ks[64 * 65];
    __shared__ int   tp[SK];
    int bh = blockIdx.y, tid = threadIdx.x;
    int j0 = blockIdx.x * 64;
    const float* Qb = g_Q + (size_t)bh * LL * HD;
    const float* Kb = g_K + (size_t)bh * LL * HD;
    if (tid < SK) tp[tid] = g_top[bh * SK + tid];
    __syncthreads();
    for (int i = tid; i < SK * HD; i += 256) {
        int u = i >> 6, dd = i & 63;
        qs[i] = Qb[(size_t)tp[u] * HD + dd];
    }
    for (int i = tid; i < 64 * HD; i += 256) {
        int jj = i >> 6, dd = i & 63;
        ks[jj * 65 + dd] = Kb[(size_t)(j0 + jj) * HD + dd];
    }
    __syncthreads();
    int key = tid & 63, ug = tid >> 6;
    int j = j0 + key;
    for (int u = ug; u < SK; u += 4) {
        float acc = 0.f;
        #pragma unroll 16
        for (int dd = 0; dd < HD; dd++) acc += qs[u * HD + dd] * ks[key * 65 + dd];
        float e = (j > tp[u]) ? 0.f : __expf(acc * 0.125f);
        g_sc[((size_t)bh * SK + u) * LL + j] = e;
        float r = e;
        #pragma unroll
        for (int o = 16; o; o >>= 1) r += __shfl_xor_sync(0xffffffffu, r, o);
        if ((tid & 31) == 0) atomicAdd(&g_rowsum[bh * SK + u], r);
    }
}

// ---------------------------------------------------------------------------
// K8: upd partials: block = (j-segment of 256 keys, bh).
// ---------------------------------------------------------------------------
__global__ __launch_bounds__(256) void k_updpart() {
    __shared__ float vs[32 * HD];
    __shared__ float ps[SK * 32];
    int jseg = blockIdx.x, bh = blockIdx.y, tid = threadIdx.x;
    const float* Vb = g_V + (size_t)bh * LL * HD;
    int d = tid & 63, ug = tid >> 6;
    float acc[12];
    #pragma unroll
    for (int c = 0; c < 12; c++) acc[c] = 0.f;
    for (int jc = jseg * 256; jc < (jseg + 1) * 256; jc += 32) {
        for (int i = tid; i < 32 * HD; i += 256) vs[i] = Vb[(size_t)jc * HD + i];
        for (int i = tid; i < SK * 32; i += 256) {
            int u = i >> 5, jj = i & 31;
            ps[i] = g_sc[((size_t)bh * SK + u) * LL + jc + jj];
        }
        __syncthreads();
        for (int jj = 0; jj < 32; jj++) {
            float vv = vs[jj * HD + d];
            int c = 0;
            for (int u = ug; u < SK; u += 4, c++) acc[c] += ps[u * 32 + jj] * vv;
        }
        __syncthreads();
    }
    int c = 0;
    for (int u = ug; u < SK; u += 4, c++)
        g_part[(((size_t)bh * JSEGS + jseg) * SK + u) * HD + d] = acc[c];
}

// K9: reduce partials, normalize by row sum, scatter into out at top rows.
__global__ void k_scatter(float* __restrict__ out) {
    int u = blockIdx.x, bh = blockIdx.y, d = threadIdx.x;
    float s = 0.f;
    for (int seg = 0; seg < JSEGS; seg++)
        s += g_part[(((size_t)bh * JSEGS + seg) * SK + u) * HD + d];
    s *= (1.f / g_rowsum[bh * SK + u]);
    int b_ = bh >> 3, h = bh & 7, l = g_top[bh * SK + u];
    out[((size_t)b_ * LL + l) * DM + h * HD + d] = s;
}

// ---------------------------------------------------------------------------
extern "C" void kernel_launch(void* const* d_in, const int* in_sizes, int n_in,
                              void* d_out, int out_size) {
    const float* queries = (const float*)d_in[0];
    const float* keys    = (const float*)d_in[1];
    const float* values  = (const float*)d_in[2];
    const float* Wq = (const float*)d_in[3];
    const float* bq = (const float*)d_in[4];
    const float* Wk = (const float*)d_in[5];
    const float* bk = (const float*)d_in[6];
    const float* Wv = (const float*)d_in[7];
    const float* bv = (const float*)d_in[8];
    const int*   idx = (const int*)d_in[9];
    float* out = (float*)d_out;

    cudaFuncSetAttribute(k_proj_mma2, cudaFuncAttributeMaxDynamicSharedMemorySize,
                         PROJ_SMEM_BYTES);

    k_splitX<<<dim3(MM * DM / 4 / 256, 3), 256>>>(queries, keys, values);
    k_splitW<<<dim3(16, 16, 3), dim3(32, 8)>>>(Wq, Wk, Wv);
    k_proj_mma2<<<dim3(DM / 128, MM / 128, 3), 256, PROJ_SMEM_BYTES>>>(bq, bk, bv);
    k_mscore<<<dim3(LL / 32, BH), 256>>>(idx);
    k_topk<<<BH, 256>>>();
    k_cumsum_local<<<dim3(NSEG, BH), 256>>>(out);
    k_cumsum_off<<<dim3(NSEG, BH), 256>>>(out);
    k_scores<<<dim3(LL / 64, BH), 256>>>();
    k_updpart<<<dim3(JSEGS, BH), 256>>>();
    k_scatter<<<dim3(SK, BH), 64>>>(out);
}

// round 10
// speedup vs baseline: 2.6898x; 1.3744x over previous
#include <cuda_runtime.h>
#include <cuda_fp16.h>
#include <math.h>
#include <stdint.h>

// Problem constants (fixed shapes)
#define BB 2
#define LL 4096
#define DM 512
#define NH 8
#define HD 64
#define SK 45                 // sample_k = n_top = min(5*ceil(ln(4096)), 4096)
#define BH (BB*NH)
#define NSEG 32
#define SEGL (LL/NSEG)        // 128
#define JSEGS 16              // j-splits for upd partial sums
#define MM (BB*LL)            // 8192 rows

// Scratch (device globals — no allocation allowed in kernel_launch)
__device__ float g_Q[BB*NH*LL*HD];
__device__ float g_K[BB*NH*LL*HD];
__device__ float g_V[BB*NH*LL*HD];
__device__ float g_m[BH*LL];
__device__ int   g_top[BH*SK];
__device__ float g_seg[BH*NSEG*HD];
__device__ float g_sc[BH*SK*LL];
__device__ float g_part[BH*JSEGS*SK*HD];
__device__ float g_rowsum[BH*SK];
// fp16 split scratch (hi/lo pair; 16B-aligned for cp.async)
__device__ __align__(16) uint16_t g_Ah[3u*MM*DM];
__device__ __align__(16) uint16_t g_Al[3u*MM*DM];
__device__ __align__(16) uint16_t g_Wh[3u*DM*DM];   // transposed: [n][k]
__device__ __align__(16) uint16_t g_Wl[3u*DM*DM];

// ===========================================================================
// helpers (legacy mma.sync path — compiles at compute_103 baseline)
// ===========================================================================
__device__ __forceinline__ void mma_f16(float c[4], uint32_t a0, uint32_t a1,
                                        uint32_t a2, uint32_t a3,
                                        uint32_t b0, uint32_t b1) {
    asm volatile(
        "mma.sync.aligned.m16n8k16.row.col.f32.f16.f16.f32 "
        "{%0,%1,%2,%3}, {%4,%5,%6,%7}, {%8,%9}, {%0,%1,%2,%3};"
        : "+f"(c[0]), "+f"(c[1]), "+f"(c[2]), "+f"(c[3])
        : "r"(a0), "r"(a1), "r"(a2), "r"(a3), "r"(b0), "r"(b1));
}
__device__ __forceinline__ uint32_t smem_addr_u32(const void* p) {
    uint32_t a;
    asm("{ .reg .u64 t; cvta.to.shared.u64 t, %1; cvt.u32.u64 %0, t; }" : "=r"(a) : "l"(p));
    return a;
}
#define CP_ASYNC16(dst, src) \
    asm volatile("cp.async.cg.shared.global [%0], [%1], 16;" :: "r"(dst), "l"(src))
#define CP_COMMIT() asm volatile("cp.async.commit_group;" ::: "memory")
#define CP_WAIT(n)  asm volatile("cp.async.wait_group %0;" :: "n"(n) : "memory")
#define LDSM_X4(r0, r1, r2, r3, addr) \
    asm volatile("ldmatrix.sync.aligned.m8n8.x4.shared.b16 {%0,%1,%2,%3}, [%4];" \
                 : "=r"(r0), "=r"(r1), "=r"(r2), "=r"(r3) : "r"(addr))

__device__ __forceinline__ void split_h(float x, uint16_t& h, uint16_t& l) {
    __half a0 = __float2half_rn(x);
    float r = x - __half2float(a0);
    __half a1 = __float2half_rn(r);
    h = __half_as_ushort(a0);
    l = __half_as_ushort(a1);
}

// ---------------------------------------------------------------------------
// K0a: elementwise fp16 hi/lo split of the three input matrices (coalesced).
// Each thread handles 8 floats -> 16B hi + 16B lo.
// ---------------------------------------------------------------------------
__global__ __launch_bounds__(256) void k_splitX(
    const float* __restrict__ X0, const float* __restrict__ X1, const float* __restrict__ X2)
{
    int z = blockIdx.y;
    const float* X = (z == 0) ? X0 : (z == 1) ? X1 : X2;
    size_t i = (size_t)blockIdx.x * 256 + threadIdx.x;      // group-of-8 index
    float4 v0 = ((const float4*)X)[2 * i];
    float4 v1 = ((const float4*)X)[2 * i + 1];
    float xs[8] = {v0.x, v0.y, v0.z, v0.w, v1.x, v1.y, v1.z, v1.w};
    uint16_t h[8], l[8];
    #pragma unroll
    for (int j = 0; j < 8; j++) split_h(xs[j], h[j], l[j]);
    uint4 hp, lp;
    hp.x = h[0] | ((uint32_t)h[1] << 16); hp.y = h[2] | ((uint32_t)h[3] << 16);
    hp.z = h[4] | ((uint32_t)h[5] << 16); hp.w = h[6] | ((uint32_t)h[7] << 16);
    lp.x = l[0] | ((uint32_t)l[1] << 16); lp.y = l[2] | ((uint32_t)l[3] << 16);
    lp.z = l[4] | ((uint32_t)l[5] << 16); lp.w = l[6] | ((uint32_t)l[7] << 16);
    size_t base = (size_t)z * MM * DM / 8;
    ((uint4*)g_Ah)[base + i] = hp;
    ((uint4*)g_Al)[base + i] = lp;
}

// ---------------------------------------------------------------------------
// K0b: W transpose + split: g_W{h,l}[z][n][k] = split(W[k][n]).
// ---------------------------------------------------------------------------
__global__ __launch_bounds__(256) void k_splitW(
    const float* __restrict__ W0, const float* __restrict__ W1, const float* __restrict__ W2)
{
    __shared__ float t[32][33];
    int z = blockIdx.z;
    const float* W = (z == 0) ? W0 : (z == 1) ? W1 : W2;
    int bx = blockIdx.x * 32;   // n tile
    int by = blockIdx.y * 32;   // k tile
    int tx = threadIdx.x, ty = threadIdx.y;   // (32, 8)
    #pragma unroll
    for (int r = ty; r < 32; r += 8)
        t[r][tx] = W[(size_t)(by + r) * DM + bx + tx];
    __syncthreads();
    size_t zoff = (size_t)z * DM * DM;
    #pragma unroll
    for (int r = ty; r < 32; r += 8) {
        float x = t[tx][r];                   // = W[by+tx][bx+r]
        uint16_t h, l;
        split_h(x, h, l);
        g_Wh[zoff + (size_t)(bx + r) * DM + by + tx] = h;
        g_Wl[zoff + (size_t)(bx + r) * DM + by + tx] = l;
    }
}

// ---------------------------------------------------------------------------
// K1: projection GEMM, 3xFP16 mma.sync (a0b0 + a1b0 + a0b1), cp.async double
// buffer + ldmatrix. CTA tile 128x128, BK=32, 8 warps 2(m)x4(n), warp 64x32.
// SMEM halfs row stride 40 (r*20 mod 32 distinct -> conflict-free ldmatrix).
// ---------------------------------------------------------------------------
#define RSTH 40                        // row stride in halfs
#define TILE_H (128 * RSTH)            // 5120 halfs per tile
#define STAGE_H (4 * TILE_H)           // 20480 halfs per stage
#define PROJ_SMEM_BYTES (2 * STAGE_H * 2)   // 81920 B

__device__ __forceinline__ void ld_stage(uint32_t smb,
    const uint16_t* __restrict__ Ah, const uint16_t* __restrict__ Al,
    const uint16_t* __restrict__ Bh, const uint16_t* __restrict__ Bl,
    int k0, int tid)
{
    #pragma unroll
    for (int t = 0; t < 2; t++) {
        int idx = tid + t * 256;             // 0..511
        int row = idx >> 2;                  // 0..127
        int ch  = (idx & 3) * 8;             // half offset 0,8,16,24
        uint32_t d = smb + (uint32_t)(row * RSTH + ch) * 2;
        size_t s = (size_t)row * DM + k0 + ch;
        CP_ASYNC16(d,                    Ah + s);
        CP_ASYNC16(d + TILE_H * 2,       Al + s);
        CP_ASYNC16(d + 2 * TILE_H * 2,   Bh + s);
        CP_ASYNC16(d + 3 * TILE_H * 2,   Bl + s);
    }
}

__global__ __launch_bounds__(256, 2) void k_proj_mma2(
    const float* __restrict__ bq, const float* __restrict__ bk, const float* __restrict__ bv)
{
    extern __shared__ uint16_t smem_h[];
    const int z = blockIdx.z;
    const float* bias = (z == 0) ? bq : (z == 1) ? bk : bv;
    float* dst = (z == 0) ? g_Q : (z == 1) ? g_K : g_V;

    const int tid  = threadIdx.x;
    const int wid  = tid >> 5;
    const int lane = tid & 31;
    const int warp_m = wid >> 2;             // 0..1
    const int warp_n = wid & 3;              // 0..3
    const int m0 = blockIdx.y * 128;
    const int n0 = blockIdx.x * 128;

    const uint16_t* Ah = g_Ah + (size_t)z * MM * DM + (size_t)m0 * DM;
    const uint16_t* Al = g_Al + (size_t)z * MM * DM + (size_t)m0 * DM;
    const uint16_t* Bh = g_Wh + (size_t)z * DM * DM + (size_t)n0 * DM;
    const uint16_t* Bl = g_Wl + (size_t)z * DM * DM + (size_t)n0 * DM;

    const uint32_t smb = smem_addr_u32(smem_h);

    float c[4][4][4];
    #pragma unroll
    for (int mt = 0; mt < 4; mt++)
        #pragma unroll
        for (int nt = 0; nt < 4; nt++)
            #pragma unroll
            for (int i = 0; i < 4; i++) c[mt][nt][i] = 0.f;

    // ldmatrix per-lane address components (halfs)
    const int l7 = lane & 7;
    const int aRow  = warp_m * 64 + l7 + ((lane >> 3) & 1) * 8;   // + mt*16
    const int aColH = ((lane >> 4) & 1) * 8;                      // + kb
    const int bRow  = warp_n * 32 + l7 + ((lane >> 4) & 1) * 8;   // + pair*16
    const int bColH = ((lane >> 3) & 1) * 8;                      // + kb

    ld_stage(smb, Ah, Al, Bh, Bl, 0, tid);
    CP_COMMIT();

    const int NCHUNK = DM / 32;              // 16
    for (int ck = 0; ck < NCHUNK; ck++) {
        if (ck + 1 < NCHUNK) {
            ld_stage(smb + ((ck + 1) & 1) * STAGE_H * 2, Ah, Al, Bh, Bl, (ck + 1) * 32, tid);
            CP_COMMIT();
            CP_WAIT(1);
        } else {
            CP_WAIT(0);
        }
        __syncthreads();

        const uint32_t stage = smb + (ck & 1) * STAGE_H * 2;
        #pragma unroll
        for (int prod = 0; prod < 3; prod++) {
            // products: (Ah,Bh), (Al,Bh), (Ah,Bl)
            const uint32_t aoff = stage + (prod == 1 ? TILE_H * 2 : 0);
            const uint32_t boff = stage + 2 * TILE_H * 2 + (prod == 2 ? TILE_H * 2 : 0);
            #pragma unroll
            for (int ks = 0; ks < 2; ks++) {
                const int kb = ks * 16;
                uint32_t af[4][4];
                #pragma unroll
                for (int mt = 0; mt < 4; mt++) {
                    uint32_t addr = aoff + (uint32_t)(((aRow + mt * 16) * RSTH) + kb + aColH) * 2;
                    LDSM_X4(af[mt][0], af[mt][1], af[mt][2], af[mt][3], addr);
                }
                uint32_t bf[4][2];
                #pragma unroll
                for (int pr = 0; pr < 2; pr++) {
                    uint32_t addr = boff + (uint32_t)(((bRow + pr * 16) * RSTH) + kb + bColH) * 2;
                    LDSM_X4(bf[pr * 2][0], bf[pr * 2][1], bf[pr * 2 + 1][0], bf[pr * 2 + 1][1], addr);
                }
                #pragma unroll
                for (int mt = 0; mt < 4; mt++)
                    #pragma unroll
                    for (int nt = 0; nt < 4; nt++)
                        mma_f16(c[mt][nt], af[mt][0], af[mt][1], af[mt][2], af[mt][3],
                                bf[nt][0], bf[nt][1]);
            }
        }
        __syncthreads();
    }

    // ---- epilogue: accum -> smem staging (stride 132 floats) -> coalesced ----
    float* stg = (float*)smem_h;             // 128 x 132 floats = 67584 B <= 81920
    const int fr = lane >> 2, fk = lane & 3;
    #pragma unroll
    for (int mt = 0; mt < 4; mt++) {
        #pragma unroll
        for (int nt = 0; nt < 4; nt++) {
            int m = warp_m * 64 + mt * 16 + fr;
            int n = warp_n * 32 + nt * 8 + fk * 2;
            stg[m * 132 + n]           = c[mt][nt][0];
            stg[m * 132 + n + 1]       = c[mt][nt][1];
            stg[(m + 8) * 132 + n]     = c[mt][nt][2];
            stg[(m + 8) * 132 + n + 1] = c[mt][nt][3];
        }
    }
    __syncthreads();
    for (int i = tid; i < 128 * 128; i += 256) {
        int row = i >> 7, col = i & 127;
        int n = n0 + col;
        int h = n >> 6, dd = n & 63;
        int mi = m0 + row;
        int b_ = mi >> 12, l = mi & (LL - 1);
        dst[(((size_t)(b_ * NH + h) * LL) + l) * HD + dd] = stg[row * 132 + col] + bias[n];
    }
}

// ---------------------------------------------------------------------------
// K2: m[bh][l] = max_s(q_l . k_{idx[l,s]}) - sum_s(...)/L
// 8 lanes per row, 4 rows per warp, float4 loads, idx prefetched to smem.
// ---------------------------------------------------------------------------
__global__ __launch_bounds__(256) void k_mscore(const int* __restrict__ idx) {
    __shared__ int sidx[32 * SK];            // 32 rows' samples (contiguous in gmem)
    int bh = blockIdx.y;
    int l0 = blockIdx.x * 32;
    int tid = threadIdx.x;
    for (int i = tid; i < 32 * SK; i += 256) sidx[i] = idx[l0 * SK + i];
    __syncthreads();

    int wid = tid >> 5, lane = tid & 31;
    int grp = lane >> 3, sub = lane & 7;
    int lrel = wid * 4 + grp;
    int l = l0 + lrel;
    const float* Qb = g_Q + (size_t)bh * LL * HD;
    const float* Kb = g_K + (size_t)bh * LL * HD;
    float4 q0 = *(const float4*)&Qb[(size_t)l * HD + sub * 8];
    float4 q1 = *(const float4*)&Qb[(size_t)l * HD + sub * 8 + 4];
    const int* myidx = &sidx[lrel * SK];
    float mx = -INFINITY, sm = 0.f;
    #pragma unroll 6
    for (int s = 0; s < SK; s++) {
        int j = myidx[s];
        const float* kr = &Kb[(size_t)j * HD + sub * 8];
        float4 k0 = *(const float4*)kr;
        float4 k1 = *(const float4*)(kr + 4);
        float p = q0.x*k0.x + q0.y*k0.y + q0.z*k0.z + q0.w*k0.w
                + q1.x*k1.x + q1.y*k1.y + q1.z*k1.z + q1.w*k1.w;
        p += __shfl_xor_sync(0xffffffffu, p, 4);
        p += __shfl_xor_sync(0xffffffffu, p, 2);
        p += __shfl_xor_sync(0xffffffffu, p, 1);
        mx = fmaxf(mx, p);
        sm += p;
    }
    if (sub == 0) g_m[bh * LL + l] = mx - sm * (1.f / LL);
}

// ---------------------------------------------------------------------------
// K3: top-45 of 4096 per (b,h) via 4-pass radix threshold select.
// Output order arbitrary (downstream keyed by index value); smallest-index
// tie-break at threshold => same SET as jax.lax.top_k. Also zeroes g_rowsum.
// ---------------------------------------------------------------------------
__global__ __launch_bounds__(256) void k_topk() {
    __shared__ uint32_t keys[LL];            // 16 KB
    __shared__ uint32_t hist[256];
    __shared__ uint32_t s_prefix, s_need;
    __shared__ int s_cnt, s_eq;
    __shared__ int eq_list[256];
    int bh = blockIdx.x, tid = threadIdx.x;
    if (tid < SK) g_rowsum[bh * SK + tid] = 0.f;   // consumed by k_scores later
    for (int i = tid; i < LL; i += 256) {
        uint32_t u = __float_as_uint(g_m[bh * LL + i]);
        keys[i] = (u & 0x80000000u) ? ~u : (u | 0x80000000u);
    }
    if (tid == 0) { s_prefix = 0; s_need = SK; s_cnt = 0; s_eq = 0; }
    __syncthreads();

    for (int level = 0; level < 4; level++) {
        int shift = 24 - 8 * level;
        uint32_t pmask = (level == 0) ? 0u : (0xFFFFFFFFu << (shift + 8));
        hist[tid] = 0;
        __syncthreads();
        uint32_t prefix = s_prefix;
        for (int i = tid; i < LL; i += 256) {
            uint32_t u = keys[i];
            if ((u & pmask) == prefix) atomicAdd(&hist[(u >> shift) & 0xFFu], 1u);
        }
        __syncthreads();
        if (tid == 0) {
            uint32_t need = s_need, S = 0; int b;
            for (b = 255; b > 0; b--) {
                if (S + hist[b] >= need) break;
                S += hist[b];
            }
            s_prefix = prefix | ((uint32_t)b << shift);
            s_need = need - S;
        }
        __syncthreads();
    }
    uint32_t thresh = s_prefix;
    uint32_t need_eq = s_need;

    for (int i = tid; i < LL; i += 256) {
        uint32_t u = keys[i];
        if (u > thresh) {
            int p = atomicAdd(&s_cnt, 1);
            g_top[bh * SK + p] = i;
        } else if (u == thresh) {
            int p = atomicAdd(&s_eq, 1);
            if (p < 256) eq_list[p] = i;
        }
    }
    __syncthreads();
    if (tid == 0) {
        int E = s_eq < 256 ? s_eq : 256;
        int base = s_cnt;
        for (uint32_t t = 0; t < need_eq; t++) {
            int best = 1 << 30, bj = 0;
            for (int j2 = 0; j2 < E; j2++)
                if (eq_list[j2] < best) { best = eq_list[j2]; bj = j2; }
            g_top[bh * SK + base + t] = best;
            eq_list[bj] = 1 << 30;
        }
    }
}

// ---------------------------------------------------------------------------
// K4: segmented inclusive cumsum of V along seq (local part).
// ---------------------------------------------------------------------------
__global__ __launch_bounds__(256) void k_cumsum_local(float* __restrict__ out) {
    __shared__ float tile[SEGL * HD];
    int seg = blockIdx.x, bh = blockIdx.y, tid = threadIdx.x;
    const float* Vb = g_V + (size_t)bh * LL * HD + (size_t)seg * SEGL * HD;
    for (int i = tid; i < SEGL * HD; i += 256) tile[i] = Vb[i];
    __syncthreads();
    if (tid < HD) {
        float acc = tile[tid];
        for (int l = 1; l < SEGL; l++) { acc += tile[l * HD + tid]; tile[l * HD + tid] = acc; }
        g_seg[((size_t)bh * NSEG + seg) * HD + tid] = acc;
    }
    __syncthreads();
    int b_ = bh >> 3, h = bh & 7;
    for (int i = tid; i < SEGL * HD; i += 256) {
        int l = seg * SEGL + (i >> 6), dd = i & 63;
        out[((size_t)b_ * LL + l) * DM + h * HD + dd] = tile[i];
    }
}

// K5: add exclusive prefix of segment totals.
__global__ __launch_bounds__(256) void k_cumsum_off(float* __restrict__ out) {
    int seg = blockIdx.x, bh = blockIdx.y, tid = threadIdx.x;
    if (seg == 0) return;
    __shared__ float offs[HD];
    if (tid < HD) {
        float s = 0.f;
        for (int ss = 0; ss < seg; ss++) s += g_seg[((size_t)bh * NSEG + ss) * HD + tid];
        offs[tid] = s;
    }
    __syncthreads();
    int b_ = bh >> 3, h = bh & 7;
    for (int i = tid; i < SEGL * HD; i += 256) {
        int l = seg * SEGL + (i >> 6), dd = i & 63;
        out[((size_t)b_ * LL + l) * DM + h * HD + dd] += offs[dd];
    }
}

// ---------------------------------------------------------------------------
// K6: unnormalized attention weights: e = exp(0.125 * q_top[u] . k_j) for
// j <= tp[u], else 0. Accumulates per-(bh,u) row sums into g_rowsum.
// ---------------------------------------------------------------------------
__global__ __launch_bounds__(256) void k_scores() {
    __shared__ float qs[SK * HD];
    __shared__ float ks[64 * 65];
    __shared__ int   tp[SK];
    int bh = blockIdx.y, tid = threadIdx.x;
    int j0 = blockIdx.x * 64;
    const float* Qb = g_Q + (size_t)bh * LL * HD;
    const float* Kb = g_K + (size_t)bh * LL * HD;
    if (tid < SK) tp[tid] = g_top[bh * SK + tid];
    __syncthreads();
    for (int i = tid; i < SK * HD; i += 256) {
        int u = i >> 6, dd = i & 63;
        qs[i] = Qb[(size_t)tp[u] * HD + dd];
    }
    for (int i = tid; i < 64 * HD; i += 256) {
        int jj = i >> 6, dd = i & 63;
        ks[jj * 65 + dd] = Kb[(size_t)(j0 + jj) * HD + dd];
    }
    __syncthreads();
    int key = tid & 63, ug = tid >> 6;
    int j = j0 + key;
    for (int u = ug; u < SK; u += 4) {
        float acc = 0.f;
        #pragma unroll 16
        for (int dd = 0; dd < HD; dd++) acc += qs[u * HD + dd] * ks[key * 65 + dd];
        float e = (j > tp[u]) ? 0.f : __expf(acc * 0.125f);
        g_sc[((size_t)bh * SK + u) * LL + j] = e;
        float r = e;
        #pragma unroll
        for (int o = 16; o; o >>= 1) r += __shfl_xor_sync(0xffffffffu, r, o);
        if ((tid & 31) == 0) atomicAdd(&g_rowsum[bh * SK + u], r);
    }
}

// ---------------------------------------------------------------------------
// K8: upd partials: block = (j-segment of 256 keys, bh).
// ---------------------------------------------------------------------------
__global__ __launch_bounds__(256) void k_updpart() {
    __shared__ float vs[32 * HD];
    __shared__ float ps[SK * 32];
    int jseg = blockIdx.x, bh = blockIdx.y, tid = threadIdx.x;
    const float* Vb = g_V + (size_t)bh * LL * HD;
    int d = tid & 63, ug = tid >> 6;
    float acc[12];
    #pragma unroll
    for (int c = 0; c < 12; c++) acc[c] = 0.f;
    for (int jc = jseg * 256; jc < (jseg + 1) * 256; jc += 32) {
        for (int i = tid; i < 32 * HD; i += 256) vs[i] = Vb[(size_t)jc * HD + i];
        for (int i = tid; i < SK * 32; i += 256) {
            int u = i >> 5, jj = i & 31;
            ps[i] = g_sc[((size_t)bh * SK + u) * LL + jc + jj];
        }
        __syncthreads();
        for (int jj = 0; jj < 32; jj++) {
            float vv = vs[jj * HD + d];
            int c = 0;
            for (int u = ug; u < SK; u += 4, c++) acc[c] += ps[u * 32 + jj] * vv;
        }
        __syncthreads();
    }
    int c = 0;
    for (int u = ug; u < SK; u += 4, c++)
        g_part[(((size_t)bh * JSEGS + jseg) * SK + u) * HD + d] = acc[c];
}

// K9: reduce partials, normalize by row sum, scatter into out at top rows.
__global__ void k_scatter(float* __restrict__ out) {
    int u = blockIdx.x, bh = blockIdx.y, d = threadIdx.x;
    float s = 0.f;
    for (int seg = 0; seg < JSEGS; seg++)
        s += g_part[(((size_t)bh * JSEGS + seg) * SK + u) * HD + d];
    s *= (1.f / g_rowsum[bh * SK + u]);
    int b_ = bh >> 3, h = bh & 7, l = g_top[bh * SK + u];
    out[((size_t)b_ * LL + l) * DM + h * HD + d] = s;
}

// ---------------------------------------------------------------------------
extern "C" void kernel_launch(void* const* d_in, const int* in_sizes, int n_in,
                              void* d_out, int out_size) {
    const float* queries = (const float*)d_in[0];
    const float* keys    = (const float*)d_in[1];
    const float* values  = (const float*)d_in[2];
    const float* Wq = (const float*)d_in[3];
    const float* bq = (const float*)d_in[4];
    const float* Wk = (const float*)d_in[5];
    const float* bk = (const float*)d_in[6];
    const float* Wv = (const float*)d_in[7];
    const float* bv = (const float*)d_in[8];
    const int*   idx = (const int*)d_in[9];
    float* out = (float*)d_out;

    cudaFuncSetAttribute(k_proj_mma2, cudaFuncAttributeMaxDynamicSharedMemorySize,
                         PROJ_SMEM_BYTES);

    k_splitX<<<dim3(MM * DM / 8 / 256, 3), 256>>>(queries, keys, values);
    k_splitW<<<dim3(16, 16, 3), dim3(32, 8)>>>(Wq, Wk, Wv);
    k_proj_mma2<<<dim3(DM / 128, MM / 128, 3), 256, PROJ_SMEM_BYTES>>>(bq, bk, bv);
    k_mscore<<<dim3(LL / 32, BH), 256>>>(idx);
    k_topk<<<BH, 256>>>();
    k_cumsum_local<<<dim3(NSEG, BH), 256>>>(out);
    k_cumsum_off<<<dim3(NSEG, BH), 256>>>(out);
    k_scores<<<dim3(LL / 64, BH), 256>>>();
    k_updpart<<<dim3(JSEGS, BH), 256>>>();
    k_scatter<<<dim3(SK, BH), 64>>>(out);
}

// round 11
// speedup vs baseline: 2.9937x; 1.1130x over previous
#include <cuda_runtime.h>
#include <cuda_fp16.h>
#include <math.h>
#include <stdint.h>

// Problem constants (fixed shapes)
#define BB 2
#define LL 4096
#define DM 512
#define NH 8
#define HD 64
#define SK 45                 // sample_k = n_top = min(5*ceil(ln(4096)), 4096)
#define BH (BB*NH)
#define NSEG 32
#define SEGL (LL/NSEG)        // 128
#define JSEGS 16              // j-splits for upd partial sums
#define MM (BB*LL)            // 8192 rows

// Scratch (device globals — no allocation allowed in kernel_launch)
__device__ float g_Q[BB*NH*LL*HD];
__device__ float g_K[BB*NH*LL*HD];
__device__ float g_V[BB*NH*LL*HD];
__device__ float g_m[BH*LL];
__device__ int   g_top[BH*SK];
__device__ float g_seg[BH*NSEG*HD];
__device__ float g_part[BH*JSEGS*SK*HD];
__device__ float g_rowsum[BH*SK];
// fp16 split scratch (hi/lo pair; 16B-aligned for cp.async)
__device__ __align__(16) uint16_t g_Ah[3u*MM*DM];
__device__ __align__(16) uint16_t g_Al[3u*MM*DM];
__device__ __align__(16) uint16_t g_Wh[3u*DM*DM];   // transposed: [n][k]
__device__ __align__(16) uint16_t g_Wl[3u*DM*DM];

// ===========================================================================
// helpers (legacy mma.sync path — compiles at compute_103 baseline)
// ===========================================================================
__device__ __forceinline__ void mma_f16(float c[4], uint32_t a0, uint32_t a1,
                                        uint32_t a2, uint32_t a3,
                                        uint32_t b0, uint32_t b1) {
    asm volatile(
        "mma.sync.aligned.m16n8k16.row.col.f32.f16.f16.f32 "
        "{%0,%1,%2,%3}, {%4,%5,%6,%7}, {%8,%9}, {%0,%1,%2,%3};"
        : "+f"(c[0]), "+f"(c[1]), "+f"(c[2]), "+f"(c[3])
        : "r"(a0), "r"(a1), "r"(a2), "r"(a3), "r"(b0), "r"(b1));
}
__device__ __forceinline__ uint32_t smem_addr_u32(const void* p) {
    uint32_t a;
    asm("{ .reg .u64 t; cvta.to.shared.u64 t, %1; cvt.u32.u64 %0, t; }" : "=r"(a) : "l"(p));
    return a;
}
#define CP_ASYNC16(dst, src) \
    asm volatile("cp.async.cg.shared.global [%0], [%1], 16;" :: "r"(dst), "l"(src))
#define CP_COMMIT() asm volatile("cp.async.commit_group;" ::: "memory")
#define CP_WAIT(n)  asm volatile("cp.async.wait_group %0;" :: "n"(n) : "memory")
#define LDSM_X4(r0, r1, r2, r3, addr) \
    asm volatile("ldmatrix.sync.aligned.m8n8.x4.shared.b16 {%0,%1,%2,%3}, [%4];" \
                 : "=r"(r0), "=r"(r1), "=r"(r2), "=r"(r3) : "r"(addr))

__device__ __forceinline__ void split_h(float x, uint16_t& h, uint16_t& l) {
    __half a0 = __float2half_rn(x);
    float r = x - __half2float(a0);
    __half a1 = __float2half_rn(r);
    h = __half_as_ushort(a0);
    l = __half_as_ushort(a1);
}

// ---------------------------------------------------------------------------
// K0a: elementwise fp16 hi/lo split of the three input matrices (coalesced).
// ---------------------------------------------------------------------------
__global__ __launch_bounds__(256) void k_splitX(
    const float* __restrict__ X0, const float* __restrict__ X1, const float* __restrict__ X2)
{
    int z = blockIdx.y;
    const float* X = (z == 0) ? X0 : (z == 1) ? X1 : X2;
    size_t i = (size_t)blockIdx.x * 256 + threadIdx.x;      // group-of-8 index
    float4 v0 = ((const float4*)X)[2 * i];
    float4 v1 = ((const float4*)X)[2 * i + 1];
    float xs[8] = {v0.x, v0.y, v0.z, v0.w, v1.x, v1.y, v1.z, v1.w};
    uint16_t h[8], l[8];
    #pragma unroll
    for (int j = 0; j < 8; j++) split_h(xs[j], h[j], l[j]);
    uint4 hp, lp;
    hp.x = h[0] | ((uint32_t)h[1] << 16); hp.y = h[2] | ((uint32_t)h[3] << 16);
    hp.z = h[4] | ((uint32_t)h[5] << 16); hp.w = h[6] | ((uint32_t)h[7] << 16);
    lp.x = l[0] | ((uint32_t)l[1] << 16); lp.y = l[2] | ((uint32_t)l[3] << 16);
    lp.z = l[4] | ((uint32_t)l[5] << 16); lp.w = l[6] | ((uint32_t)l[7] << 16);
    size_t base = (size_t)z * MM * DM / 8;
    ((uint4*)g_Ah)[base + i] = hp;
    ((uint4*)g_Al)[base + i] = lp;
}

// ---------------------------------------------------------------------------
// K0b: W transpose + split: g_W{h,l}[z][n][k] = split(W[k][n]).
// ---------------------------------------------------------------------------
__global__ __launch_bounds__(256) void k_splitW(
    const float* __restrict__ W0, const float* __restrict__ W1, const float* __restrict__ W2)
{
    __shared__ float t[32][33];
    int z = blockIdx.z;
    const float* W = (z == 0) ? W0 : (z == 1) ? W1 : W2;
    int bx = blockIdx.x * 32;   // n tile
    int by = blockIdx.y * 32;   // k tile
    int tx = threadIdx.x, ty = threadIdx.y;   // (32, 8)
    #pragma unroll
    for (int r = ty; r < 32; r += 8)
        t[r][tx] = W[(size_t)(by + r) * DM + bx + tx];
    __syncthreads();
    size_t zoff = (size_t)z * DM * DM;
    #pragma unroll
    for (int r = ty; r < 32; r += 8) {
        float x = t[tx][r];                   // = W[by+tx][bx+r]
        uint16_t h, l;
        split_h(x, h, l);
        g_Wh[zoff + (size_t)(bx + r) * DM + by + tx] = h;
        g_Wl[zoff + (size_t)(bx + r) * DM + by + tx] = l;
    }
}

// ---------------------------------------------------------------------------
// K1: projection GEMM, 3xFP16 mma.sync (a0b0 + a1b0 + a0b1), cp.async double
// buffer + ldmatrix. CTA tile 128x128, BK=32, 8 warps 2(m)x4(n), warp 64x32.
// ---------------------------------------------------------------------------
#define RSTH 40                        // row stride in halfs
#define TILE_H (128 * RSTH)            // 5120 halfs per tile
#define STAGE_H (4 * TILE_H)           // 20480 halfs per stage
#define PROJ_SMEM_BYTES (2 * STAGE_H * 2)   // 81920 B

__device__ __forceinline__ void ld_stage(uint32_t smb,
    const uint16_t* __restrict__ Ah, const uint16_t* __restrict__ Al,
    const uint16_t* __restrict__ Bh, const uint16_t* __restrict__ Bl,
    int k0, int tid)
{
    #pragma unroll
    for (int t = 0; t < 2; t++) {
        int idx = tid + t * 256;             // 0..511
        int row = idx >> 2;                  // 0..127
        int ch  = (idx & 3) * 8;             // half offset 0,8,16,24
        uint32_t d = smb + (uint32_t)(row * RSTH + ch) * 2;
        size_t s = (size_t)row * DM + k0 + ch;
        CP_ASYNC16(d,                    Ah + s);
        CP_ASYNC16(d + TILE_H * 2,       Al + s);
        CP_ASYNC16(d + 2 * TILE_H * 2,   Bh + s);
        CP_ASYNC16(d + 3 * TILE_H * 2,   Bl + s);
    }
}

__global__ __launch_bounds__(256, 2) void k_proj_mma2(
    const float* __restrict__ bq, const float* __restrict__ bk, const float* __restrict__ bv)
{
    extern __shared__ uint16_t smem_h[];
    const int z = blockIdx.z;
    const float* bias = (z == 0) ? bq : (z == 1) ? bk : bv;
    float* dst = (z == 0) ? g_Q : (z == 1) ? g_K : g_V;

    const int tid  = threadIdx.x;
    const int wid  = tid >> 5;
    const int lane = tid & 31;
    const int warp_m = wid >> 2;             // 0..1
    const int warp_n = wid & 3;              // 0..3
    const int m0 = blockIdx.y * 128;
    const int n0 = blockIdx.x * 128;

    const uint16_t* Ah = g_Ah + (size_t)z * MM * DM + (size_t)m0 * DM;
    const uint16_t* Al = g_Al + (size_t)z * MM * DM + (size_t)m0 * DM;
    const uint16_t* Bh = g_Wh + (size_t)z * DM * DM + (size_t)n0 * DM;
    const uint16_t* Bl = g_Wl + (size_t)z * DM * DM + (size_t)n0 * DM;

    const uint32_t smb = smem_addr_u32(smem_h);

    float c[4][4][4];
    #pragma unroll
    for (int mt = 0; mt < 4; mt++)
        #pragma unroll
        for (int nt = 0; nt < 4; nt++)
            #pragma unroll
            for (int i = 0; i < 4; i++) c[mt][nt][i] = 0.f;

    const int l7 = lane & 7;
    const int aRow  = warp_m * 64 + l7 + ((lane >> 3) & 1) * 8;
    const int aColH = ((lane >> 4) & 1) * 8;
    const int bRow  = warp_n * 32 + l7 + ((lane >> 4) & 1) * 8;
    const int bColH = ((lane >> 3) & 1) * 8;

    ld_stage(smb, Ah, Al, Bh, Bl, 0, tid);
    CP_COMMIT();

    const int NCHUNK = DM / 32;              // 16
    for (int ck = 0; ck < NCHUNK; ck++) {
        if (ck + 1 < NCHUNK) {
            ld_stage(smb + ((ck + 1) & 1) * STAGE_H * 2, Ah, Al, Bh, Bl, (ck + 1) * 32, tid);
            CP_COMMIT();
            CP_WAIT(1);
        } else {
            CP_WAIT(0);
        }
        __syncthreads();

        const uint32_t stage = smb + (ck & 1) * STAGE_H * 2;
        #pragma unroll
        for (int prod = 0; prod < 3; prod++) {
            const uint32_t aoff = stage + (prod == 1 ? TILE_H * 2 : 0);
            const uint32_t boff = stage + 2 * TILE_H * 2 + (prod == 2 ? TILE_H * 2 : 0);
            #pragma unroll
            for (int ks = 0; ks < 2; ks++) {
                const int kb = ks * 16;
                uint32_t af[4][4];
                #pragma unroll
                for (int mt = 0; mt < 4; mt++) {
                    uint32_t addr = aoff + (uint32_t)(((aRow + mt * 16) * RSTH) + kb + aColH) * 2;
                    LDSM_X4(af[mt][0], af[mt][1], af[mt][2], af[mt][3], addr);
                }
                uint32_t bf[4][2];
                #pragma unroll
                for (int pr = 0; pr < 2; pr++) {
                    uint32_t addr = boff + (uint32_t)(((bRow + pr * 16) * RSTH) + kb + bColH) * 2;
                    LDSM_X4(bf[pr * 2][0], bf[pr * 2][1], bf[pr * 2 + 1][0], bf[pr * 2 + 1][1], addr);
                }
                #pragma unroll
                for (int mt = 0; mt < 4; mt++)
                    #pragma unroll
                    for (int nt = 0; nt < 4; nt++)
                        mma_f16(c[mt][nt], af[mt][0], af[mt][1], af[mt][2], af[mt][3],
                                bf[nt][0], bf[nt][1]);
            }
        }
        __syncthreads();
    }

    // ---- epilogue: accum -> smem staging (stride 132 floats) -> coalesced ----
    float* stg = (float*)smem_h;             // 128 x 132 floats = 67584 B <= 81920
    const int fr = lane >> 2, fk = lane & 3;
    #pragma unroll
    for (int mt = 0; mt < 4; mt++) {
        #pragma unroll
        for (int nt = 0; nt < 4; nt++) {
            int m = warp_m * 64 + mt * 16 + fr;
            int n = warp_n * 32 + nt * 8 + fk * 2;
            stg[m * 132 + n]           = c[mt][nt][0];
            stg[m * 132 + n + 1]       = c[mt][nt][1];
            stg[(m + 8) * 132 + n]     = c[mt][nt][2];
            stg[(m + 8) * 132 + n + 1] = c[mt][nt][3];
        }
    }
    __syncthreads();
    for (int i = tid; i < 128 * 128; i += 256) {
        int row = i >> 7, col = i & 127;
        int n = n0 + col;
        int h = n >> 6, dd = n & 63;
        int mi = m0 + row;
        int b_ = mi >> 12, l = mi & (LL - 1);
        dst[(((size_t)(b_ * NH + h) * LL) + l) * HD + dd] = stg[row * 132 + col] + bias[n];
    }
}

// ---------------------------------------------------------------------------
// K2 (fused): blockIdx.x < 128 -> mscore; else -> cumsum_local (independent
// work sharing one launch so the short cumsum fills SMs under the
// latency-bound mscore).
// ---------------------------------------------------------------------------
__global__ __launch_bounds__(256) void k_fused1(const int* __restrict__ idx,
                                                float* __restrict__ out) {
    __shared__ __align__(16) char sb[(SEGL * HD + 4 * HD) * 4];   // 33 KB
    int tid = threadIdx.x;
    int bh = blockIdx.y;
    if (blockIdx.x < LL / 32) {
        // ---------------- mscore ----------------
        int* sidx = (int*)sb;                 // 32*SK ints
        int l0 = blockIdx.x * 32;
        for (int i = tid; i < 32 * SK; i += 256) sidx[i] = idx[l0 * SK + i];
        __syncthreads();
        int wid = tid >> 5, lane = tid & 31;
        int grp = lane >> 3, sub = lane & 7;
        int lrel = wid * 4 + grp;
        int l = l0 + lrel;
        const float* Qb = g_Q + (size_t)bh * LL * HD;
        const float* Kb = g_K + (size_t)bh * LL * HD;
        float4 q0 = *(const float4*)&Qb[(size_t)l * HD + sub * 8];
        float4 q1 = *(const float4*)&Qb[(size_t)l * HD + sub * 8 + 4];
        const int* myidx = &sidx[lrel * SK];
        float mx = -INFINITY, sm = 0.f;
        #pragma unroll 6
        for (int s = 0; s < SK; s++) {
            int j = myidx[s];
            const float* kr = &Kb[(size_t)j * HD + sub * 8];
            float4 k0 = *(const float4*)kr;
            float4 k1 = *(const float4*)(kr + 4);
            float p = q0.x*k0.x + q0.y*k0.y + q0.z*k0.z + q0.w*k0.w
                    + q1.x*k1.x + q1.y*k1.y + q1.z*k1.z + q1.w*k1.w;
            p += __shfl_xor_sync(0xffffffffu, p, 4);
            p += __shfl_xor_sync(0xffffffffu, p, 2);
            p += __shfl_xor_sync(0xffffffffu, p, 1);
            mx = fmaxf(mx, p);
            sm += p;
        }
        if (sub == 0) g_m[bh * LL + l] = mx - sm * (1.f / LL);
    } else {
        // ---------------- cumsum_local (4-way parallel scan) ----------------
        int seg = blockIdx.x - LL / 32;       // 0..31
        float* tile = (float*)sb;             // SEGL*HD
        float* qtot = tile + SEGL * HD;       // 4*HD
        const float* Vb = g_V + (size_t)bh * LL * HD + (size_t)seg * SEGL * HD;
        for (int i = tid; i < SEGL * HD; i += 256) tile[i] = Vb[i];
        __syncthreads();
        int d = tid & 63, q = tid >> 6;
        float acc = 0.f;
        #pragma unroll 8
        for (int r = 0; r < 32; r++) {
            int o = (q * 32 + r) * HD + d;
            acc += tile[o];
            tile[o] = acc;
        }
        qtot[q * HD + d] = acc;
        __syncthreads();
        float pre = 0.f;
        for (int qq = 0; qq < q; qq++) pre += qtot[qq * HD + d];
        if (q == 3) g_seg[((size_t)bh * NSEG + seg) * HD + d] = pre + qtot[3 * HD + d];
        if (q) {
            #pragma unroll 8
            for (int r = 0; r < 32; r++) tile[(q * 32 + r) * HD + d] += pre;
        }
        __syncthreads();
        int b_ = bh >> 3, h = bh & 7;
        for (int i = tid; i < SEGL * HD; i += 256) {
            int l = seg * SEGL + (i >> 6), dd = i & 63;
            out[((size_t)b_ * LL + l) * DM + h * HD + dd] = tile[i];
        }
    }
}

// ---------------------------------------------------------------------------
// K3 (fused): blockIdx.x == 0 -> radix top-45 (also zeroes g_rowsum);
// blockIdx.x >= 1 -> cumsum segment-offset fix (seg = blockIdx.x).
// ---------------------------------------------------------------------------
__global__ __launch_bounds__(256) void k_fused2(float* __restrict__ out) {
    __shared__ uint32_t keys[LL];            // 16 KB
    __shared__ uint32_t hist[256];
    __shared__ uint32_t s_prefix, s_need;
    __shared__ int s_cnt, s_eq;
    __shared__ int eq_list[256];
    int tid = threadIdx.x;
    int bh = blockIdx.y;
    if (blockIdx.x == 0) {
        // ---------------- top-k ----------------
        if (tid < SK) g_rowsum[bh * SK + tid] = 0.f;
        for (int i = tid; i < LL; i += 256) {
            uint32_t u = __float_as_uint(g_m[bh * LL + i]);
            keys[i] = (u & 0x80000000u) ? ~u : (u | 0x80000000u);
        }
        if (tid == 0) { s_prefix = 0; s_need = SK; s_cnt = 0; s_eq = 0; }
        __syncthreads();
        for (int level = 0; level < 4; level++) {
            int shift = 24 - 8 * level;
            uint32_t pmask = (level == 0) ? 0u : (0xFFFFFFFFu << (shift + 8));
            hist[tid] = 0;
            __syncthreads();
            uint32_t prefix = s_prefix;
            for (int i = tid; i < LL; i += 256) {
                uint32_t u = keys[i];
                if ((u & pmask) == prefix) atomicAdd(&hist[(u >> shift) & 0xFFu], 1u);
            }
            __syncthreads();
            if (tid == 0) {
                uint32_t need = s_need, S = 0; int b;
                for (b = 255; b > 0; b--) {
                    if (S + hist[b] >= need) break;
                    S += hist[b];
                }
                s_prefix = prefix | ((uint32_t)b << shift);
                s_need = need - S;
            }
            __syncthreads();
        }
        uint32_t thresh = s_prefix;
        uint32_t need_eq = s_need;
        for (int i = tid; i < LL; i += 256) {
            uint32_t u = keys[i];
            if (u > thresh) {
                int p = atomicAdd(&s_cnt, 1);
                g_top[bh * SK + p] = i;
            } else if (u == thresh) {
                int p = atomicAdd(&s_eq, 1);
                if (p < 256) eq_list[p] = i;
            }
        }
        __syncthreads();
        if (tid == 0) {
            int E = s_eq < 256 ? s_eq : 256;
            int base = s_cnt;
            for (uint32_t t = 0; t < need_eq; t++) {
                int best = 1 << 30, bj = 0;
                for (int j2 = 0; j2 < E; j2++)
                    if (eq_list[j2] < best) { best = eq_list[j2]; bj = j2; }
                g_top[bh * SK + base + t] = best;
                eq_list[bj] = 1 << 30;
            }
        }
    } else {
        // ---------------- cumsum_off ----------------
        int seg = blockIdx.x;                 // 1..31
        float* offs = (float*)hist;           // reuse
        if (tid < HD) {
            float s = 0.f;
            for (int ss = 0; ss < seg; ss++) s += g_seg[((size_t)bh * NSEG + ss) * HD + tid];
            offs[tid] = s;
        }
        __syncthreads();
        int b_ = bh >> 3, h = bh & 7;
        for (int i = tid; i < SEGL * HD; i += 256) {
            int l = seg * SEGL + (i >> 6), dd = i & 63;
            out[((size_t)b_ * LL + l) * DM + h * HD + dd] += offs[dd];
        }
    }
}

// ---------------------------------------------------------------------------
// K4: fused scores+updpart. Block = (jseg of 256 keys, bh). For each 64-key
// sub-chunk: e[u][key] = exp(q_top[u].k_key / 8) (0 past causal limit), then
// immediately acc[u][d] += e . V. Fully-masked u rows (tp[u] < jc) skipped.
// Row sums accumulated in smem then one global atomic per u.
// ---------------------------------------------------------------------------
#define SU_QS 0
#define SU_KS (SK*HD)                 // 2880
#define SU_VS (SU_KS + 64*65)         // 7040
#define SU_ES (SU_VS + 64*64)         // 11136
#define SU_FLOATS (SU_ES + SK*64)     // 14016
#define SU_BYTES (SU_FLOATS * 4)      // 56064

__global__ __launch_bounds__(256) void k_scoreupd() {
    extern __shared__ float sm[];
    __shared__ int   tp[SK];
    __shared__ float rs[SK];
    int jseg = blockIdx.x, bh = blockIdx.y, tid = threadIdx.x;
    const float* Qb = g_Q + (size_t)bh * LL * HD;
    const float* Kb = g_K + (size_t)bh * LL * HD;
    const float* Vb = g_V + (size_t)bh * LL * HD;
    if (tid < SK) { tp[tid] = g_top[bh * SK + tid]; rs[tid] = 0.f; }
    __syncthreads();
    float* qs = sm + SU_QS;
    float* ks = sm + SU_KS;
    float* vs = sm + SU_VS;
    float* es = sm + SU_ES;
    for (int i = tid; i < SK * HD; i += 256)
        qs[i] = Qb[(size_t)tp[i >> 6] * HD + (i & 63)];
    int key = tid & 63, ug = tid >> 6;
    float acc[12];
    #pragma unroll
    for (int c = 0; c < 12; c++) acc[c] = 0.f;

    for (int sc = 0; sc < 4; sc++) {
        int jc = jseg * 256 + sc * 64;
        __syncthreads();                      // protect ks/vs/es reuse
        for (int i = tid; i < 64 * HD; i += 256) {
            int jj = i >> 6, dd = i & 63;
            ks[jj * 65 + dd] = Kb[(size_t)(jc + jj) * HD + dd];
            vs[i] = Vb[(size_t)jc * HD + i];
        }
        __syncthreads();
        // scores for this 64-key chunk
        for (int u = ug; u < SK; u += 4) {
            int t = tp[u];
            if (t >= jc) {                    // warp-uniform
                float a = 0.f;
                #pragma unroll 16
                for (int dd = 0; dd < HD; dd++) a += qs[u * HD + dd] * ks[key * 65 + dd];
                float e = (jc + key > t) ? 0.f : __expf(a * 0.125f);
                es[u * 64 + key] = e;
                float r = e;
                #pragma unroll
                for (int o = 16; o; o >>= 1) r += __shfl_xor_sync(0xffffffffu, r, o);
                if ((tid & 31) == 0) atomicAdd(&rs[u], r);
            } else {
                es[u * 64 + key] = 0.f;
            }
        }
        __syncthreads();
        // accumulate e . V (key doubles as d here)
        int c = 0;
        for (int u = ug; u < SK; u += 4, c++) {
            if (tp[u] >= jc) {                // warp-uniform
                float a = acc[c];
                #pragma unroll 16
                for (int jj = 0; jj < 64; jj++) a += es[u * 64 + jj] * vs[jj * 64 + key];
                acc[c] = a;
            }
        }
    }
    __syncthreads();
    int c = 0;
    for (int u = ug; u < SK; u += 4, c++)
        g_part[(((size_t)bh * JSEGS + jseg) * SK + u) * HD + key] = acc[c];
    if (tid < SK && rs[tid] != 0.f) atomicAdd(&g_rowsum[bh * SK + tid], rs[tid]);
}

// K5: reduce partials, normalize by row sum, scatter into out at top rows.
__global__ void k_scatter(float* __restrict__ out) {
    int u = blockIdx.x, bh = blockIdx.y, d = threadIdx.x;
    float s = 0.f;
    for (int seg = 0; seg < JSEGS; seg++)
        s += g_part[(((size_t)bh * JSEGS + seg) * SK + u) * HD + d];
    s *= (1.f / g_rowsum[bh * SK + u]);
    int b_ = bh >> 3, h = bh & 7, l = g_top[bh * SK + u];
    out[((size_t)b_ * LL + l) * DM + h * HD + d] = s;
}

// ---------------------------------------------------------------------------
extern "C" void kernel_launch(void* const* d_in, const int* in_sizes, int n_in,
                              void* d_out, int out_size) {
    const float* queries = (const float*)d_in[0];
    const float* keys    = (const float*)d_in[1];
    const float* values  = (const float*)d_in[2];
    const float* Wq = (const float*)d_in[3];
    const float* bq = (const float*)d_in[4];
    const float* Wk = (const float*)d_in[5];
    const float* bk = (const float*)d_in[6];
    const float* Wv = (const float*)d_in[7];
    const float* bv = (const float*)d_in[8];
    const int*   idx = (const int*)d_in[9];
    float* out = (float*)d_out;

    cudaFuncSetAttribute(k_proj_mma2, cudaFuncAttributeMaxDynamicSharedMemorySize,
                         PROJ_SMEM_BYTES);
    cudaFuncSetAttribute(k_scoreupd, cudaFuncAttributeMaxDynamicSharedMemorySize,
                         SU_BYTES);

    k_splitX<<<dim3(MM * DM / 8 / 256, 3), 256>>>(queries, keys, values);
    k_splitW<<<dim3(16, 16, 3), dim3(32, 8)>>>(Wq, Wk, Wv);
    k_proj_mma2<<<dim3(DM / 128, MM / 128, 3), 256, PROJ_SMEM_BYTES>>>(bq, bk, bv);
    k_fused1<<<dim3(LL / 32 + NSEG, BH), 256>>>(idx, out);
    k_fused2<<<dim3(NSEG, BH), 256>>>(out);
    k_scoreupd<<<dim3(JSEGS, BH), 256, SU_BYTES>>>();
    k_scatter<<<dim3(SK, BH), 64>>>(out);
}